// round 10
// baseline (speedup 1.0000x reference)
#include <cuda_runtime.h>
#include <cuda_bf16.h>
#include <cstdint>
#include <cstddef>

#define HW    10000
#define WID   100
#define NPAD  10240
#define KTOT  2304
#define WROWS 3584
#define SLOTS 6
#define CSTR  ((size_t)NPAD * KTOT)   // col-slot stride (elements)
#define FSTR  ((size_t)256 * HW)      // feature-chain stride

typedef __nv_bfloat16 bf16;

__device__ bf16 g_wh[WROWS * KTOT];              // 16.5 MB
__device__ bf16 g_wl[WROWS * KTOT];
__device__ bf16 g_colh[SLOTS * CSTR];            // 283 MB
__device__ bf16 g_coll[SLOTS * CSTR];
__device__ bf16 g_cth[2 * CSTR];                 // cls cat (94 MB)
__device__ bf16 g_ctl[2 * CSTR];
__device__ bf16 g_crh[2 * CSTR];                 // reg cat
__device__ bf16 g_crl[2 * CSTR];
__device__ float g_ftA[4 * 256 * HW];            // tower ping
__device__ float g_ftB[4 * 256 * HW];            // tower pong (final: cf0,rf0,cf1,rf1)
__device__ float g_boxreg[2 * 36 * HW];
__device__ float g_refine[2 * 36 * HW];

__constant__ float c_AW[9] = {
    2.8284271247461903f, 2.0f, 1.4142135623730951f,
    3.5635948725613580f, 2.5198420997897464f, 1.7817974362806790f,
    4.4898481932374910f, 3.1748021039363988f, 2.2449240966187455f};
__constant__ float c_AH[9] = {
    1.4142135623730951f, 2.0f, 2.8284271247461903f,
    1.7817974362806790f, 2.5198420997897464f, 3.5635948725613580f,
    2.2449240966187455f, 3.1748021039363988f, 4.4898481932374910f};

__device__ __forceinline__ uint32_t smem_u32(const void* p) {
    uint32_t a;
    asm("{ .reg .u64 t; cvta.to.shared.u64 t, %1; cvt.u32.u64 %0, t; }" : "=r"(a) : "l"(p));
    return a;
}
__device__ __forceinline__ void cp16(uint32_t dst, const void* src) {
    asm volatile("cp.async.cg.shared.global [%0], [%1], 16;" :: "r"(dst), "l"(src));
}
__device__ __forceinline__ void ldmx4(uint32_t* r, uint32_t addr) {
    asm volatile("ldmatrix.sync.aligned.m8n8.x4.shared.b16 {%0,%1,%2,%3}, [%4];"
                 : "=r"(r[0]), "=r"(r[1]), "=r"(r[2]), "=r"(r[3]) : "r"(addr));
}
__device__ __forceinline__ void mma16816(float* c, const uint32_t* a, uint32_t b0, uint32_t b1) {
    asm volatile("mma.sync.aligned.m16n8k16.row.col.f32.bf16.bf16.f32 "
                 "{%0,%1,%2,%3}, {%4,%5,%6,%7}, {%8,%9}, {%0,%1,%2,%3};"
                 : "+f"(c[0]), "+f"(c[1]), "+f"(c[2]), "+f"(c[3])
                 : "r"(a[0]), "r"(a[1]), "r"(a[2]), "r"(a[3]), "r"(b0), "r"(b1));
}
__device__ __forceinline__ uint32_t bpack(bf16 a, bf16 b) {
    return (uint32_t)__bfloat16_as_ushort(a) | ((uint32_t)__bfloat16_as_ushort(b) << 16);
}
// smem tile: 128 rows x 4 chunks of 16B (BK=32), XOR-4 swizzle
__device__ __forceinline__ uint32_t sw_off(int r, int c) {
    return (uint32_t)((r * 4 + (c ^ (r & 3))) << 4);
}

#define TILE_B 8192
#define STAGE_B (4 * TILE_B)
#define NSTG 3
#define NK   72
#define SMEM_SZ (NSTG * STAGE_B)     // 96 KB -> 2 CTAs/SM

// flags: 1=bias 2=relu 4=cat-out 8=tower(z-indexed A/bias)
__global__ __launch_bounds__(256, 2) void mma_gemm(
    const bf16* __restrict__ Ah0, const bf16* __restrict__ Al0, int arowE, int arowO,
    const bf16* __restrict__ Bh0, const bf16* __restrict__ Bl0,
    const float* __restrict__ biasE, const float* __restrict__ biasO,
    float* __restrict__ outF, size_t outStride,
    bf16* __restrict__ outTh, bf16* __restrict__ outTl,
    int M, int flags, int zoff)
{
    extern __shared__ char smem[];
    const uint32_t sb = smem_u32(smem);
    const int tid = threadIdx.x, lane = tid & 31, w = tid >> 5;
    const int wm = w >> 2, wn = w & 3;
    const int m0 = blockIdx.y * 128, n0 = blockIdx.x * 128;
    const int zl = blockIdx.z;          // local z (col slot)
    const int z = zl + zoff;            // global z (cat / out index)

    const bool odd = (flags & 8) && (z & 1);
    const int arow = odd ? arowO : arowE;
    const float* bias = odd ? biasO : biasE;

    const bf16* srcs[4] = {
        Ah0 + ((size_t)arow + m0) * KTOT, Al0 + ((size_t)arow + m0) * KTOT,
        Bh0 + (size_t)zl * CSTR + (size_t)n0 * KTOT,
        Bl0 + (size_t)zl * CSTR + (size_t)n0 * KTOT};

    float acc[4][4][4];
#pragma unroll
    for (int i = 0; i < 4; i++)
#pragma unroll
        for (int j = 0; j < 4; j++)
#pragma unroll
            for (int q = 0; q < 4; q++) acc[i][j][q] = 0.f;

    const int ra = (lane & 15);
    const int ca = lane >> 4;
    const int rb = (lane & 7) + ((lane >> 4) << 3);
    const int cb = (lane >> 3) & 1;

#define LOAD_STAGE(s, k0) do { \
    _Pragma("unroll") \
    for (int t = 0; t < 4; t++) { \
        const uint32_t base = sb + (uint32_t)((s) * STAGE_B + t * TILE_B); \
        _Pragma("unroll") \
        for (int h = 0; h < 2; h++) { \
            const int q = tid + h * 256; \
            const int r = q >> 2, c = q & 3; \
            cp16(base + sw_off(r, c), srcs[t] + (size_t)r * KTOT + (k0) + c * 8); \
        } \
    } \
} while (0)

    LOAD_STAGE(0, 0);
    asm volatile("cp.async.commit_group;" ::: "memory");
    LOAD_STAGE(1, 32);
    asm volatile("cp.async.commit_group;" ::: "memory");

    for (int kc = 0; kc < NK; kc++) {
        asm volatile("cp.async.wait_group 1;" ::: "memory");
        __syncthreads();

        const uint32_t bA  = sb + (uint32_t)((kc % NSTG) * STAGE_B);
        const uint32_t bAl = bA + TILE_B;
        const uint32_t bBh = bA + 2 * TILE_B;
        const uint32_t bBl = bA + 3 * TILE_B;
#pragma unroll
        for (int kh = 0; kh < 2; kh++) {
            uint32_t fbh[2][4], fbl[2][4];
#pragma unroll
            for (int nt2 = 0; nt2 < 2; nt2++) {
                const int rr = wn * 32 + nt2 * 16 + rb;
                const int cc = kh * 2 + cb;
                ldmx4(fbh[nt2], bBh + sw_off(rr, cc));
                ldmx4(fbl[nt2], bBl + sw_off(rr, cc));
            }
#pragma unroll
            for (int mt = 0; mt < 4; mt++) {
                uint32_t fah[4], fal[4];
                const int rr = wm * 64 + mt * 16 + ra;
                const int cc = kh * 2 + ca;
                ldmx4(fah, bA  + sw_off(rr, cc));
                ldmx4(fal, bAl + sw_off(rr, cc));
#pragma unroll
                for (int nt = 0; nt < 4; nt++) {
                    const uint32_t b0h = fbh[nt >> 1][(nt & 1) * 2];
                    const uint32_t b1h = fbh[nt >> 1][(nt & 1) * 2 + 1];
                    const uint32_t b0l = fbl[nt >> 1][(nt & 1) * 2];
                    const uint32_t b1l = fbl[nt >> 1][(nt & 1) * 2 + 1];
                    mma16816(acc[mt][nt], fah, b0h, b1h);
                    mma16816(acc[mt][nt], fah, b0l, b1l);
                    mma16816(acc[mt][nt], fal, b0h, b1h);
                }
            }
        }
        if (kc + 2 < NK) LOAD_STAGE((kc + 2) % NSTG, (kc + 2) * 32);
        asm volatile("cp.async.commit_group;" ::: "memory");
    }
    __syncthreads();

    const int group = lane >> 2, tid4 = lane & 3;

    if (flags & 4) {
        const int bpp = z / 9, ap = z % 9;
        float* smf = (float*)smem;
#pragma unroll
        for (int mt = 0; mt < 4; mt++) {
#pragma unroll
            for (int nt = 0; nt < 4; nt++) {
                const int ml = wm * 64 + mt * 16 + group;
                const int nl = wn * 32 + nt * 8 + tid4 * 2;
                smf[nl * 128 + ml]           = acc[mt][nt][0];
                smf[(nl + 1) * 128 + ml]     = acc[mt][nt][1];
                smf[nl * 128 + ml + 8]       = acc[mt][nt][2];
                smf[(nl + 1) * 128 + ml + 8] = acc[mt][nt][3];
            }
        }
        __syncthreads();
        const int nl = tid >> 1, half = tid & 1;
        const size_t row_out = (size_t)(bpp * NPAD + n0 + nl) * KTOT + ap * 256 + m0 + half * 64;
        const float* row = smf + nl * 128 + half * 64;
        bf16* oh = outTh + row_out;
        bf16* ol = outTl + row_out;
#pragma unroll
        for (int g = 0; g < 8; g++) {
            bf16 hs[8], ls[8];
#pragma unroll
            for (int j = 0; j < 8; j++) {
                const float v = fmaxf(row[g * 8 + j], 0.f);
                hs[j] = __float2bfloat16(v);
                ls[j] = __float2bfloat16(v - __bfloat162float(hs[j]));
            }
            *(uint4*)(oh + g * 8) = make_uint4(bpack(hs[0],hs[1]), bpack(hs[2],hs[3]),
                                               bpack(hs[4],hs[5]), bpack(hs[6],hs[7]));
            *(uint4*)(ol + g * 8) = make_uint4(bpack(ls[0],ls[1]), bpack(ls[2],ls[3]),
                                               bpack(ls[4],ls[5]), bpack(ls[6],ls[7]));
        }
    } else {
        float* oF = outF + (size_t)z * outStride;
#pragma unroll
        for (int mt = 0; mt < 4; mt++) {
            const int mA = m0 + wm * 64 + mt * 16 + group;
            const int mB = mA + 8;
            const float bvA = ((flags & 1) && mA < M) ? bias[mA] : 0.f;
            const float bvB = ((flags & 1) && mB < M) ? bias[mB] : 0.f;
#pragma unroll
            for (int nt = 0; nt < 4; nt++) {
                const int n = n0 + wn * 32 + nt * 8 + tid4 * 2;
#pragma unroll
                for (int e = 0; e < 2; e++) {
                    if (n + e < HW) {
                        if (mA < M) {
                            float v = acc[mt][nt][e] + bvA;
                            if (flags & 2) v = fmaxf(v, 0.f);
                            oF[(size_t)mA * HW + n + e] = v;
                        }
                        if (mB < M) {
                            float v = acc[mt][nt][2 + e] + bvB;
                            if (flags & 2) v = fmaxf(v, 0.f);
                            oF[(size_t)mB * HW + n + e] = v;
                        }
                    }
                }
            }
        }
    }
#undef LOAD_STAGE
}

__global__ void wsplit_kernel(const float* __restrict__ src, bf16* __restrict__ h,
                              bf16* __restrict__ l, int M, int Mp)
{
    const int idx = blockIdx.x * blockDim.x + threadIdx.x;
    if (idx >= Mp * KTOT) return;
    const float v = (idx / KTOT < M) ? src[idx] : 0.f;
    const bf16 hh = __float2bfloat16(v);
    h[idx] = hh;
    l[idx] = __float2bfloat16(v - __bfloat162float(hh));
}

// batched: z = blockIdx.y ; input = in + (z >> zdiv) * inStride ; out slot z
__global__ __launch_bounds__(256) void im2col3x3_bf16(
    const float* __restrict__ in, int zdiv, size_t inStride,
    bf16* __restrict__ ch, bf16* __restrict__ cl)
{
    const int z = blockIdx.y;
    const int idx = blockIdx.x * 256 + threadIdx.x;
    if (idx >= NPAD * 32) return;
    const int p = idx % NPAD, cblk = idx / NPAD;
    const float* inz = in + (size_t)(z >> zdiv) * inStride;
    bf16* oh = ch + (size_t)z * CSTR + (size_t)p * KTOT + cblk * 72;
    bf16* ol = cl + (size_t)z * CSTR + (size_t)p * KTOT + cblk * 72;
    if (p >= HW) {
        const uint4 zz = make_uint4(0, 0, 0, 0);
#pragma unroll
        for (int g = 0; g < 9; g++) { *(uint4*)(oh + g * 8) = zz; *(uint4*)(ol + g * 8) = zz; }
        return;
    }
    const int y = p / WID, x = p % WID;
#pragma unroll 1
    for (int g = 0; g < 9; g++) {
        bf16 hs[8], ls[8];
#pragma unroll
        for (int j = 0; j < 8; j++) {
            const int e = g * 8 + j, cc = e / 9, k = e - cc * 9;
            const int yy = y + k / 3 - 1, xx = x + k % 3 - 1;
            float v = 0.f;
            if (yy >= 0 && yy < WID && xx >= 0 && xx < WID)
                v = inz[(size_t)(cblk * 8 + cc) * HW + yy * WID + xx];
            hs[j] = __float2bfloat16(v);
            ls[j] = __float2bfloat16(v - __bfloat162float(hs[j]));
        }
        *(uint4*)(oh + g * 8) = make_uint4(bpack(hs[0],hs[1]), bpack(hs[2],hs[3]),
                                           bpack(hs[4],hs[5]), bpack(hs[6],hs[7]));
        *(uint4*)(ol + g * 8) = make_uint4(bpack(ls[0],ls[1]), bpack(ls[2],ls[3]),
                                           bpack(ls[4],ls[5]), bpack(ls[6],ls[7]));
    }
}

// batched deform: global z = zoff + blockIdx.y ; writes LOCAL slot blockIdx.y of ch/cl
__global__ __launch_bounds__(256) void im2col_def_bf16(
    const float* __restrict__ ft, int t, const float* __restrict__ boxreg,
    bf16* __restrict__ ch, bf16* __restrict__ cl, int zoff)
{
    const int zl = blockIdx.y;
    const int z = zl + zoff;
    const int bpp = z / 9, ap = z % 9;
    const int nn = ap * 2 + bpp, bb = nn / 9, aa = nn % 9;
    const float aw = c_AW[aa], ah_ = c_AH[aa];
    const int idx = blockIdx.x * 256 + threadIdx.x;
    if (idx >= NPAD * 32) return;
    const int p = idx % NPAD, cblk = idx / NPAD;
    bf16* oh = ch + (size_t)zl * CSTR + (size_t)p * KTOT + cblk * 72;
    bf16* ol = cl + (size_t)zl * CSTR + (size_t)p * KTOT + cblk * 72;
    if (p >= HW) {
        const uint4 zz = make_uint4(0, 0, 0, 0);
#pragma unroll
        for (int g = 0; g < 9; g++) { *(uint4*)(oh + g * 8) = zz; *(uint4*)(ol + g * 8) = zz; }
        return;
    }
    const float* feat = ft + (size_t)(bpp * 2 + t) * FSTR;
    const float* br = boxreg + (size_t)bb * 36 * HW + (size_t)aa * 4 * HW + p;
    const int y = p / WID, x = p % WID;
    const float r0 = br[0], r1 = br[HW], r2 = br[2 * HW], r3 = br[3 * HW];
    const float whx = aw * expf(r2), why = ah_ * expf(r3);
    const float tlx = aw * r0 - 0.5f * whx, tly = ah_ * r1 - 0.5f * why;
    const float gxv[3] = {tlx, tlx + 0.5f * whx, tlx + whx};
    const float gyv[3] = {tly, tly + 0.5f * why, tly + why};
    int O00[9], O01[9], O10[9], O11[9];
    float W00[9], W01[9], W10[9], W11[9];
#pragma unroll
    for (int i = 0; i < 3; i++) {
        const float pxf = (float)x + gyv[i];
        const float x0f = floorf(pxf);
        const float lx = pxf - x0f;
        const int ix0 = (int)x0f;
        const bool vx0 = (ix0 >= 0) && (ix0 < WID), vx1 = (ix0 + 1 >= 0) && (ix0 + 1 < WID);
        const int xc0 = min(max(ix0, 0), WID - 1), xc1 = min(max(ix0 + 1, 0), WID - 1);
#pragma unroll
        for (int j = 0; j < 3; j++) {
            const int k = i * 3 + j;
            const float pyf = (float)y + gxv[j];
            const float y0f = floorf(pyf);
            const float ly = pyf - y0f;
            const int iy0 = (int)y0f;
            const bool vy0 = (iy0 >= 0) && (iy0 < WID), vy1 = (iy0 + 1 >= 0) && (iy0 + 1 < WID);
            const int yc0 = min(max(iy0, 0), WID - 1), yc1 = min(max(iy0 + 1, 0), WID - 1);
            O00[k] = yc0 * WID + xc0; O01[k] = yc0 * WID + xc1;
            O10[k] = yc1 * WID + xc0; O11[k] = yc1 * WID + xc1;
            W00[k] = (vy0 && vx0) ? (1.f - ly) * (1.f - lx) : 0.f;
            W01[k] = (vy0 && vx1) ? (1.f - ly) * lx : 0.f;
            W10[k] = (vy1 && vx0) ? ly * (1.f - lx) : 0.f;
            W11[k] = (vy1 && vx1) ? ly * lx : 0.f;
        }
    }
#pragma unroll 1
    for (int g = 0; g < 9; g++) {
        bf16 hs[8], ls[8];
#pragma unroll
        for (int j = 0; j < 8; j++) {
            const int e = g * 8 + j, cc = e / 9, k = e - cc * 9;
            const float* f = feat + (size_t)(cblk * 8 + cc) * HW;
            const float v = W00[k]*f[O00[k]] + W01[k]*f[O01[k]] + W10[k]*f[O10[k]] + W11[k]*f[O11[k]];
            hs[j] = __float2bfloat16(v);
            ls[j] = __float2bfloat16(v - __bfloat162float(hs[j]));
        }
        *(uint4*)(oh + g * 8) = make_uint4(bpack(hs[0],hs[1]), bpack(hs[2],hs[3]),
                                           bpack(hs[4],hs[5]), bpack(hs[6],hs[7]));
        *(uint4*)(ol + g * 8) = make_uint4(bpack(ls[0],ls[1]), bpack(ls[2],ls[3]),
                                           bpack(ls[4],ls[5]), bpack(ls[6],ls[7]));
    }
}

__global__ void delta_kernel(const float* __restrict__ boxreg, const float* __restrict__ refine,
                             float* __restrict__ out)
{
    const int idx = blockIdx.x * blockDim.x + threadIdx.x;
    if (idx >= 2 * 36 * HW) return;
    const int p = idx % HW, ch = (idx / HW) % 36, b = idx / (36 * HW), c = ch & 3;
    const float o1 = boxreg[((size_t)b * 36 + ch) * HW + p];
    const float o2 = refine[((size_t)b * 36 + ch) * HW + p];
    float v;
    if (c < 2) v = o1 + expf(boxreg[((size_t)b * 36 + ch + 2) * HW + p]) * o2;
    else       v = o1 + o2;
    out[idx] = v;
}

#define W_CLS   0
#define W_REG   1024
#define W_PRED  2048
#define W_DCLS  2176
#define W_DREG  2432
#define W_LOGIT 2688
#define W_REFIN 3456

// host-side stream/event resources (host objects only; no device memory)
static cudaStream_t s_gather = nullptr, s_head = nullptr;
static cudaEvent_t s_evG[12], s_evM[12], s_evFork, s_evJoin, s_evH;
static void ensure_streams() {
    if (!s_gather) {
        cudaStreamCreateWithFlags(&s_gather, cudaStreamNonBlocking);
        cudaStreamCreateWithFlags(&s_head, cudaStreamNonBlocking);
        for (int i = 0; i < 12; i++) {
            cudaEventCreateWithFlags(&s_evG[i], cudaEventDisableTiming);
            cudaEventCreateWithFlags(&s_evM[i], cudaEventDisableTiming);
        }
        cudaEventCreateWithFlags(&s_evFork, cudaEventDisableTiming);
        cudaEventCreateWithFlags(&s_evJoin, cudaEventDisableTiming);
        cudaEventCreateWithFlags(&s_evH, cudaEventDisableTiming);
    }
}

extern "C" void kernel_launch(void* const* d_in, const int* in_sizes, int n_in,
                              void* d_out, int out_size)
{
    const float* x        = (const float*)d_in[0];
    const float* cls_w    = (const float*)d_in[1];
    const float* cls_b    = (const float*)d_in[2];
    const float* reg_w    = (const float*)d_in[3];
    const float* reg_b    = (const float*)d_in[4];
    const float* pred_w   = (const float*)d_in[5];
    const float* pred_b   = (const float*)d_in[6];
    const float* dcls_w   = (const float*)d_in[7];
    const float* dreg_w   = (const float*)d_in[8];
    const float* logit_w  = (const float*)d_in[9];
    const float* logit_b  = (const float*)d_in[10];
    const float* refine_w = (const float*)d_in[11];
    const float* refine_b = (const float*)d_in[12];

    bf16 *wh, *wl, *colh, *coll, *cth, *ctl, *crh, *crl;
    float *ftA, *ftB, *boxreg, *refine;
    cudaGetSymbolAddress((void**)&wh, g_wh);
    cudaGetSymbolAddress((void**)&wl, g_wl);
    cudaGetSymbolAddress((void**)&colh, g_colh);
    cudaGetSymbolAddress((void**)&coll, g_coll);
    cudaGetSymbolAddress((void**)&cth, g_cth);
    cudaGetSymbolAddress((void**)&ctl, g_ctl);
    cudaGetSymbolAddress((void**)&crh, g_crh);
    cudaGetSymbolAddress((void**)&crl, g_crl);
    cudaGetSymbolAddress((void**)&ftA, g_ftA);
    cudaGetSymbolAddress((void**)&ftB, g_ftB);
    cudaGetSymbolAddress((void**)&boxreg, g_boxreg);
    cudaGetSymbolAddress((void**)&refine, g_refine);

    cudaFuncSetAttribute(mma_gemm, cudaFuncAttributeMaxDynamicSharedMemorySize, SMEM_SZ);
    ensure_streams();

    auto wsplit = [&](const float* src, int rowoff, int M, int Mp) {
        wsplit_kernel<<<(Mp * KTOT + 255) / 256, 256>>>(
            src, wh + (size_t)rowoff * KTOT, wl + (size_t)rowoff * KTOT, M, Mp);
    };
    // ours #0, #1 — so ours #2/#3 (first im2col / first mma_gemm) land at
    // process launch index 5/6 where ncu's -s 5 -c 1 samples (harness prepends ~3)
    wsplit(cls_w, W_CLS, 1024, 1024);
    wsplit(reg_w, W_REG, 1024, 1024);

    // ---- towers: 4 layers, 4 chains (z = b*2 + tower) batched per layer ----
    const dim3 icg(NPAD * 32 / 256, 4);
    const float* lin[4] = {x, ftA, ftB, ftA};
    float* lout[4] = {ftA, ftB, ftA, ftB};
    for (int layer = 0; layer < 4; layer++) {
        im2col3x3_bf16<<<icg, 256>>>(lin[layer], layer == 0 ? 1 : 0, FSTR, colh, coll);
        dim3 grid(NPAD / 128, 2, 4);
        mma_gemm<<<grid, 256, SMEM_SZ>>>(
            wh, wl, W_CLS + layer * 256, W_REG + layer * 256,
            colh, coll, cls_b + layer * 256, reg_b + layer * 256,
            lout[layer], FSTR, nullptr, nullptr, 256, 1 | 2 | 8, 0);
    }

    // remaining weight splits (first use is pred / deform / heads)
    wsplit(pred_w, W_PRED, 36, 128);
    wsplit(dcls_w, W_DCLS, 256, 256);
    wsplit(dreg_w, W_DREG, 256, 256);
    wsplit(logit_w, W_LOGIT, 720, 768);
    wsplit(refine_w, W_REFIN, 36, 128);

    // ---- pred conv on rf chains (ftB slots 1, 3) ----
    {
        dim3 icg2(NPAD * 32 / 256, 2);
        im2col3x3_bf16<<<icg2, 256>>>(ftB + FSTR, 0, 2 * FSTR, colh, coll);
        dim3 grid(NPAD / 128, 1, 2);
        mma_gemm<<<grid, 256, SMEM_SZ>>>(
            wh, wl, W_PRED, W_PRED, colh, coll, pred_b, pred_b,
            boxreg, (size_t)36 * HW, nullptr, nullptr, 36, 1, 0);
    }

    float* logits_out = (float*)d_out;
    float* delta_out = logits_out + (size_t)2 * 720 * HW;

    // ---- deform: 12 pipelined phases (3 slots each), gathers on side stream;
    //      logit head launched early on s_head once all cls cat (phases 0-5) done ----
    {
        cudaEventRecord(s_evFork, 0);
        cudaStreamWaitEvent(s_gather, s_evFork, 0);
        const dim3 icg3(NPAD * 32 / 256, 3);
        const dim3 grid(NPAD / 128, 2, 3);
        for (int i = 0; i < 12; i++) {
            const int t = i / 6;            // 0 = cls, 1 = reg
            const int base = (i % 6) * 3;   // global z offset
            const int half = (i & 1) * 3;   // col slot half (double buffer)
            bf16* bh = colh + (size_t)half * CSTR;
            bf16* bl = coll + (size_t)half * CSTR;
            if (i >= 2) cudaStreamWaitEvent(s_gather, s_evM[i - 2], 0);
            im2col_def_bf16<<<icg3, 256, 0, s_gather>>>(ftB, t, boxreg, bh, bl, base);
            cudaEventRecord(s_evG[i], s_gather);
            cudaStreamWaitEvent(0, s_evG[i], 0);
            mma_gemm<<<grid, 256, SMEM_SZ>>>(
                wh, wl, t == 0 ? W_DCLS : W_DREG, t == 0 ? W_DCLS : W_DREG,
                bh, bl, nullptr, nullptr, nullptr, 0,
                t == 0 ? cth : crh, t == 0 ? ctl : crl, 256, 4, base);
            cudaEventRecord(s_evM[i], 0);
            if (i == 5) {
                // all cls cat written -> logit head overlaps reg deform phases
                cudaStreamWaitEvent(s_head, s_evM[5], 0);
                dim3 gl(NPAD / 128, 6, 2);
                mma_gemm<<<gl, 256, SMEM_SZ, s_head>>>(
                    wh, wl, W_LOGIT, W_LOGIT, cth, ctl, logit_b, logit_b,
                    logits_out, (size_t)720 * HW, nullptr, nullptr, 720, 1, 0);
                cudaEventRecord(s_evH, s_head);
            }
        }
        cudaEventRecord(s_evJoin, s_gather);
        cudaStreamWaitEvent(0, s_evJoin, 0);
        cudaStreamWaitEvent(0, s_evH, 0);
    }

    // ---- refine head (needs all reg cat) ----
    {
        dim3 gr(NPAD / 128, 1, 2);
        mma_gemm<<<gr, 256, SMEM_SZ>>>(
            wh, wl, W_REFIN, W_REFIN, crh, crl, refine_b, refine_b,
            refine, (size_t)36 * HW, nullptr, nullptr, 36, 1, 0);
    }

    delta_kernel<<<(2 * 36 * HW + 255) / 256, 256>>>(boxreg, refine, delta_out);
}

// round 11
// speedup vs baseline: 1.2550x; 1.2550x over previous
#include <cuda_runtime.h>
#include <cuda_bf16.h>
#include <cstdint>
#include <cstddef>

#define HW    10000
#define WID   100
#define NPAD  10240
#define KTOT  2304
#define WROWS 3584
#define SLOTS 6
#define CSTR  ((size_t)NPAD * KTOT)
#define CH112 11312                       // channel stride: 101 padded rows (last = zero guard)
#define NPIX  11200                       // 100 rows x 112
#define FC4   ((size_t)4 * 256 * CH112)   // per-copy stride, 4-chain feature buffer
#define FC2   ((size_t)2 * 256 * CH112)   // per-copy stride, 2-chain x buffer
#define FGUARD 128

typedef __nv_bfloat16 bf16;

__device__ bf16 g_wh[WROWS * KTOT];
__device__ bf16 g_wl[WROWS * KTOT];
__device__ bf16 g_colh[SLOTS * CSTR];
__device__ bf16 g_coll[SLOTS * CSTR];
__device__ bf16 g_cth[2 * CSTR];
__device__ bf16 g_ctl[2 * CSTR];
__device__ bf16 g_crh[2 * CSTR];
__device__ bf16 g_crl[2 * CSTR];
__device__ bf16 g_xh[FGUARD + 3 * FC2 + 256];    // x split, 3 shifted copies
__device__ bf16 g_xl[FGUARD + 3 * FC2 + 256];
__device__ bf16 g_fAh[FGUARD + 3 * FC4 + 256];   // feature ping
__device__ bf16 g_fAl[FGUARD + 3 * FC4 + 256];
__device__ bf16 g_fBh[FGUARD + 3 * FC4 + 256];   // feature pong
__device__ bf16 g_fBl[FGUARD + 3 * FC4 + 256];
__device__ float g_boxreg[2 * 36 * HW];
__device__ float g_refine[2 * 36 * HW];

__constant__ float c_AW[9] = {
    2.8284271247461903f, 2.0f, 1.4142135623730951f,
    3.5635948725613580f, 2.5198420997897464f, 1.7817974362806790f,
    4.4898481932374910f, 3.1748021039363988f, 2.2449240966187455f};
__constant__ float c_AH[9] = {
    1.4142135623730951f, 2.0f, 2.8284271247461903f,
    1.7817974362806790f, 2.5198420997897464f, 3.5635948725613580f,
    2.2449240966187455f, 3.1748021039363988f, 4.4898481932374910f};
__constant__ int c_dy9[9]   = {-1,-1,-1, 0,0,0, 1,1,1};
__constant__ int c_dxsel[9] = { 0, 1, 2, 0,1,2, 0,1,2};   // dx=-1 -> copy0, 0 -> copy1, +1 -> copy2

__device__ __forceinline__ uint32_t smem_u32(const void* p) {
    uint32_t a;
    asm("{ .reg .u64 t; cvta.to.shared.u64 t, %1; cvt.u32.u64 %0, t; }" : "=r"(a) : "l"(p));
    return a;
}
__device__ __forceinline__ void cp16(uint32_t dst, const void* src) {
    asm volatile("cp.async.cg.shared.global [%0], [%1], 16;" :: "r"(dst), "l"(src));
}
__device__ __forceinline__ void ldmx4(uint32_t* r, uint32_t addr) {
    asm volatile("ldmatrix.sync.aligned.m8n8.x4.shared.b16 {%0,%1,%2,%3}, [%4];"
                 : "=r"(r[0]), "=r"(r[1]), "=r"(r[2]), "=r"(r[3]) : "r"(addr));
}
__device__ __forceinline__ void ldmx4t(uint32_t* r, uint32_t addr) {
    asm volatile("ldmatrix.sync.aligned.m8n8.x4.trans.shared.b16 {%0,%1,%2,%3}, [%4];"
                 : "=r"(r[0]), "=r"(r[1]), "=r"(r[2]), "=r"(r[3]) : "r"(addr));
}
__device__ __forceinline__ void mma16816(float* c, const uint32_t* a, uint32_t b0, uint32_t b1) {
    asm volatile("mma.sync.aligned.m16n8k16.row.col.f32.bf16.bf16.f32 "
                 "{%0,%1,%2,%3}, {%4,%5,%6,%7}, {%8,%9}, {%0,%1,%2,%3};"
                 : "+f"(c[0]), "+f"(c[1]), "+f"(c[2]), "+f"(c[3])
                 : "r"(a[0]), "r"(a[1]), "r"(a[2]), "r"(a[3]), "r"(b0), "r"(b1));
}
__device__ __forceinline__ uint32_t bpack(bf16 a, bf16 b) {
    return (uint32_t)__bfloat16_as_ushort(a) | ((uint32_t)__bfloat16_as_ushort(b) << 16);
}
// A/col smem tile: 128 rows x 4 chunks of 16B, XOR-4 swizzle
__device__ __forceinline__ uint32_t sw_off(int r, int c) {
    return (uint32_t)((r * 4 + (c ^ (r & 3))) << 4);
}
// conv B smem tile: 32 rows (ch) x 16 chunks of 16B (128 px), XOR-8 swizzle
__device__ __forceinline__ uint32_t swb_off(int r, int c) {
    return (uint32_t)((r * 16 + (c ^ (r & 7))) << 4);
}

#define TILE_B 8192
#define STAGE_B (4 * TILE_B)
#define NSTG 3
#define NK   72
#define SMEM_SZ (NSTG * STAGE_B)     // 96 KB -> 2 CTAs/SM

// ======================= explicit-col GEMM (deform + heads), unchanged R9 =======================
// flags: 1=bias 2=relu 4=cat-out 8=z-parity A/bias
__global__ __launch_bounds__(256, 2) void mma_gemm(
    const bf16* __restrict__ Ah0, const bf16* __restrict__ Al0, int arowE, int arowO,
    const bf16* __restrict__ Bh0, const bf16* __restrict__ Bl0,
    const float* __restrict__ biasE, const float* __restrict__ biasO,
    float* __restrict__ outF, size_t outStride,
    bf16* __restrict__ outTh, bf16* __restrict__ outTl,
    int M, int flags, int zoff)
{
    extern __shared__ char smem[];
    const uint32_t sb = smem_u32(smem);
    const int tid = threadIdx.x, lane = tid & 31, w = tid >> 5;
    const int wm = w >> 2, wn = w & 3;
    const int m0 = blockIdx.y * 128, n0 = blockIdx.x * 128;
    const int zl = blockIdx.z;
    const int z = zl + zoff;

    const bool odd = (flags & 8) && (z & 1);
    const int arow = odd ? arowO : arowE;
    const float* bias = odd ? biasO : biasE;

    const bf16* srcs[4] = {
        Ah0 + ((size_t)arow + m0) * KTOT, Al0 + ((size_t)arow + m0) * KTOT,
        Bh0 + (size_t)zl * CSTR + (size_t)n0 * KTOT,
        Bl0 + (size_t)zl * CSTR + (size_t)n0 * KTOT};

    float acc[4][4][4];
#pragma unroll
    for (int i = 0; i < 4; i++)
#pragma unroll
        for (int j = 0; j < 4; j++)
#pragma unroll
            for (int q = 0; q < 4; q++) acc[i][j][q] = 0.f;

    const int ra = (lane & 15);
    const int ca = lane >> 4;
    const int rb = (lane & 7) + ((lane >> 4) << 3);
    const int cb = (lane >> 3) & 1;

#define LOAD_STAGE(s, k0) do { \
    _Pragma("unroll") \
    for (int t = 0; t < 4; t++) { \
        const uint32_t base = sb + (uint32_t)((s) * STAGE_B + t * TILE_B); \
        _Pragma("unroll") \
        for (int h = 0; h < 2; h++) { \
            const int q = tid + h * 256; \
            const int r = q >> 2, c = q & 3; \
            cp16(base + sw_off(r, c), srcs[t] + (size_t)r * KTOT + (k0) + c * 8); \
        } \
    } \
} while (0)

    LOAD_STAGE(0, 0);
    asm volatile("cp.async.commit_group;" ::: "memory");
    LOAD_STAGE(1, 32);
    asm volatile("cp.async.commit_group;" ::: "memory");

    for (int kc = 0; kc < NK; kc++) {
        asm volatile("cp.async.wait_group 1;" ::: "memory");
        __syncthreads();
        const uint32_t bA  = sb + (uint32_t)((kc % NSTG) * STAGE_B);
        const uint32_t bAl = bA + TILE_B;
        const uint32_t bBh = bA + 2 * TILE_B;
        const uint32_t bBl = bA + 3 * TILE_B;
#pragma unroll
        for (int kh = 0; kh < 2; kh++) {
            uint32_t fbh[2][4], fbl[2][4];
#pragma unroll
            for (int nt2 = 0; nt2 < 2; nt2++) {
                const int rr = wn * 32 + nt2 * 16 + rb;
                const int cc = kh * 2 + cb;
                ldmx4(fbh[nt2], bBh + sw_off(rr, cc));
                ldmx4(fbl[nt2], bBl + sw_off(rr, cc));
            }
#pragma unroll
            for (int mt = 0; mt < 4; mt++) {
                uint32_t fah[4], fal[4];
                const int rr = wm * 64 + mt * 16 + ra;
                const int cc = kh * 2 + ca;
                ldmx4(fah, bA  + sw_off(rr, cc));
                ldmx4(fal, bAl + sw_off(rr, cc));
#pragma unroll
                for (int nt = 0; nt < 4; nt++) {
                    const uint32_t b0h = fbh[nt >> 1][(nt & 1) * 2];
                    const uint32_t b1h = fbh[nt >> 1][(nt & 1) * 2 + 1];
                    const uint32_t b0l = fbl[nt >> 1][(nt & 1) * 2];
                    const uint32_t b1l = fbl[nt >> 1][(nt & 1) * 2 + 1];
                    mma16816(acc[mt][nt], fah, b0h, b1h);
                    mma16816(acc[mt][nt], fah, b0l, b1l);
                    mma16816(acc[mt][nt], fal, b0h, b1h);
                }
            }
        }
        if (kc + 2 < NK) LOAD_STAGE((kc + 2) % NSTG, (kc + 2) * 32);
        asm volatile("cp.async.commit_group;" ::: "memory");
    }
    __syncthreads();
#undef LOAD_STAGE

    const int group = lane >> 2, tid4 = lane & 3;
    if (flags & 4) {
        const int bpp = z / 9, ap = z % 9;
        float* smf = (float*)smem;
#pragma unroll
        for (int mt = 0; mt < 4; mt++)
#pragma unroll
            for (int nt = 0; nt < 4; nt++) {
                const int ml = wm * 64 + mt * 16 + group;
                const int nl = wn * 32 + nt * 8 + tid4 * 2;
                smf[nl * 128 + ml]           = acc[mt][nt][0];
                smf[(nl + 1) * 128 + ml]     = acc[mt][nt][1];
                smf[nl * 128 + ml + 8]       = acc[mt][nt][2];
                smf[(nl + 1) * 128 + ml + 8] = acc[mt][nt][3];
            }
        __syncthreads();
        const int nl = tid >> 1, half = tid & 1;
        const size_t row_out = (size_t)(bpp * NPAD + n0 + nl) * KTOT + ap * 256 + m0 + half * 64;
        const float* row = smf + nl * 128 + half * 64;
        bf16* oh = outTh + row_out;
        bf16* ol = outTl + row_out;
#pragma unroll
        for (int g = 0; g < 8; g++) {
            bf16 hs[8], ls[8];
#pragma unroll
            for (int j = 0; j < 8; j++) {
                const float v = fmaxf(row[g * 8 + j], 0.f);
                hs[j] = __float2bfloat16(v);
                ls[j] = __float2bfloat16(v - __bfloat162float(hs[j]));
            }
            *(uint4*)(oh + g * 8) = make_uint4(bpack(hs[0],hs[1]), bpack(hs[2],hs[3]),
                                               bpack(hs[4],hs[5]), bpack(hs[6],hs[7]));
            *(uint4*)(ol + g * 8) = make_uint4(bpack(ls[0],ls[1]), bpack(ls[2],ls[3]),
                                               bpack(ls[4],ls[5]), bpack(ls[6],ls[7]));
        }
    } else {
        float* oF = outF + (size_t)z * outStride;
#pragma unroll
        for (int mt = 0; mt < 4; mt++) {
            const int mA = m0 + wm * 64 + mt * 16 + group;
            const int mB = mA + 8;
            const float bvA = ((flags & 1) && mA < M) ? bias[mA] : 0.f;
            const float bvB = ((flags & 1) && mB < M) ? bias[mB] : 0.f;
#pragma unroll
            for (int nt = 0; nt < 4; nt++) {
                const int n = n0 + wn * 32 + nt * 8 + tid4 * 2;
#pragma unroll
                for (int e = 0; e < 2; e++) {
                    if (n + e < HW) {
                        if (mA < M) {
                            float v = acc[mt][nt][e] + bvA;
                            if (flags & 2) v = fmaxf(v, 0.f);
                            oF[(size_t)mA * HW + n + e] = v;
                        }
                        if (mB < M) {
                            float v = acc[mt][nt][2 + e] + bvB;
                            if (flags & 2) v = fmaxf(v, 0.f);
                            oF[(size_t)mB * HW + n + e] = v;
                        }
                    }
                }
            }
        }
    }
}

// ======================= implicit conv GEMM (towers + pred) =======================
// B implicit from 3-shifted bf16 feature copies. flags: 1=bias 2=relu 8=z-parity 16=feat-out 32=fp32-p-out
__global__ __launch_bounds__(256, 2) void conv_gemm(
    const bf16* __restrict__ Ah0, const bf16* __restrict__ Al0, int arowE, int arowO,
    const bf16* __restrict__ fInH, const bf16* __restrict__ fInL,
    size_t inCopyStr, int cmul, int cadd, int cshift,
    const float* __restrict__ biasE, const float* __restrict__ biasO,
    float* __restrict__ outF, size_t outStride,
    bf16* __restrict__ oFh, bf16* __restrict__ oFl,
    int M, int flags)
{
    extern __shared__ char smem[];
    const uint32_t sb = smem_u32(smem);
    const int tid = threadIdx.x, lane = tid & 31, w = tid >> 5;
    const int wm = w >> 2, wn = w & 3;
    const int m0 = blockIdx.y * 128, n0 = blockIdx.x * 128;
    const int z = blockIdx.z;
    const int inChain = ((z * cmul) + cadd) >> cshift;

    const bool odd = (flags & 8) && (z & 1);
    const int arow = odd ? arowO : arowE;
    const float* bias = odd ? biasO : biasE;

    const bf16* srcA[2] = {Ah0 + ((size_t)arow + m0) * KTOT, Al0 + ((size_t)arow + m0) * KTOT};
    const bf16* fbase[2] = {fInH + (size_t)inChain * 256 * CH112 + n0,
                            fInL + (size_t)inChain * 256 * CH112 + n0};

    float acc[4][4][4];
#pragma unroll
    for (int i = 0; i < 4; i++)
#pragma unroll
        for (int j = 0; j < 4; j++)
#pragma unroll
            for (int q = 0; q < 4; q++) acc[i][j][q] = 0.f;

    const int ra = (lane & 15);
    const int ca = lane >> 4;

#define LOAD_CSTAGE(s, kc) do { \
    const int _t = (kc) >> 3, _c0 = ((kc) & 7) << 5; \
    const long _toff = (long)c_dxsel[_t] * (long)inCopyStr + (long)c_dy9[_t] * 112; \
    _Pragma("unroll") \
    for (int t2 = 0; t2 < 2; t2++) { \
        const uint32_t baseA = sb + (uint32_t)((s) * STAGE_B + t2 * TILE_B); \
        _Pragma("unroll") \
        for (int h = 0; h < 2; h++) { \
            const int q = tid + h * 256; \
            const int r = q >> 2, c = q & 3; \
            cp16(baseA + sw_off(r, c), srcA[t2] + (size_t)r * KTOT + (kc) * 32 + c * 8); \
        } \
    } \
    _Pragma("unroll") \
    for (int t2 = 0; t2 < 2; t2++) { \
        const uint32_t baseB = sb + (uint32_t)((s) * STAGE_B + (2 + t2) * TILE_B); \
        _Pragma("unroll") \
        for (int h = 0; h < 2; h++) { \
            const int q = tid + h * 256; \
            const int r = q >> 4, c = q & 15; \
            cp16(baseB + swb_off(r, c), fbase[t2] + _toff + (size_t)(_c0 + r) * CH112 + c * 8); \
        } \
    } \
} while (0)

    LOAD_CSTAGE(0, 0);
    asm volatile("cp.async.commit_group;" ::: "memory");
    LOAD_CSTAGE(1, 1);
    asm volatile("cp.async.commit_group;" ::: "memory");

    for (int kc = 0; kc < NK; kc++) {
        asm volatile("cp.async.wait_group 1;" ::: "memory");
        __syncthreads();
        const uint32_t bA  = sb + (uint32_t)((kc % NSTG) * STAGE_B);
        const uint32_t bAl = bA + TILE_B;
        const uint32_t bBh = bA + 2 * TILE_B;
        const uint32_t bBl = bA + 3 * TILE_B;
#pragma unroll
        for (int kh = 0; kh < 2; kh++) {
            // B frags via ldmatrix.trans from [k=32ch][n=128px] tile
            const int rowl = kh * 16 + (lane & 15);
            uint32_t fbh[2][4], fbl[2][4];
#pragma unroll
            for (int nt2 = 0; nt2 < 2; nt2++) {
                const int chunk = wn * 4 + nt2 * 2 + (lane >> 4);
                const uint32_t off = swb_off(rowl, chunk);
                ldmx4t(fbh[nt2], bBh + off);
                ldmx4t(fbl[nt2], bBl + off);
            }
#pragma unroll
            for (int mt = 0; mt < 4; mt++) {
                uint32_t fah[4], fal[4];
                const int rr = wm * 64 + mt * 16 + ra;
                const int cc = kh * 2 + ca;
                ldmx4(fah, bA  + sw_off(rr, cc));
                ldmx4(fal, bAl + sw_off(rr, cc));
#pragma unroll
                for (int nt = 0; nt < 4; nt++) {
                    const uint32_t b0h = fbh[nt >> 1][(nt & 1) * 2];
                    const uint32_t b1h = fbh[nt >> 1][(nt & 1) * 2 + 1];
                    const uint32_t b0l = fbl[nt >> 1][(nt & 1) * 2];
                    const uint32_t b1l = fbl[nt >> 1][(nt & 1) * 2 + 1];
                    mma16816(acc[mt][nt], fah, b0h, b1h);
                    mma16816(acc[mt][nt], fah, b0l, b1l);
                    mma16816(acc[mt][nt], fal, b0h, b1h);
                }
            }
        }
        if (kc + 2 < NK) LOAD_CSTAGE((kc + 2) % NSTG, kc + 2);
        asm volatile("cp.async.commit_group;" ::: "memory");
    }
    __syncthreads();
#undef LOAD_CSTAGE

    const int group = lane >> 2, tid4 = lane & 3;
#pragma unroll
    for (int mt = 0; mt < 4; mt++) {
        const int mA = m0 + wm * 64 + mt * 16 + group;
        const int mB = mA + 8;
        const float bvA = ((flags & 1) && mA < M) ? bias[mA] : 0.f;
        const float bvB = ((flags & 1) && mB < M) ? bias[mB] : 0.f;
#pragma unroll
        for (int nt = 0; nt < 4; nt++) {
            const int n = n0 + wn * 32 + nt * 8 + tid4 * 2;
#pragma unroll
            for (int e = 0; e < 2; e++) {
                const int p2 = n + e;
                if (p2 >= NPIX) continue;
                const int xq = p2 % 112;
                if (xq >= 100) continue;
                if (flags & 16) {
                    // feature out: bf16 hi/lo into 3 shifted copies (4-chain buffer)
#pragma unroll
                    for (int half = 0; half < 2; half++) {
                        const int m = half ? mB : mA;
                        float v = (half ? acc[mt][nt][2 + e] : acc[mt][nt][e]) + (half ? bvB : bvA);
                        v = fmaxf(v, 0.f);
                        const bf16 h = __float2bfloat16(v);
                        const bf16 l = __float2bfloat16(v - __bfloat162float(h));
                        const size_t cb = (size_t)(z * 256 + m) * CH112;
#pragma unroll
                        for (int j = 0; j < 3; j++) {
                            const int q = p2 - (j - 1);
                            if (q >= 0) {
                                const size_t o = (size_t)j * FC4 + cb + q;
                                oFh[o] = h;
                                oFl[o] = l;
                            }
                        }
                    }
                } else {
                    // fp32 out in original p-domain (pred conv)
                    const int p = (p2 / 112) * 100 + xq;
                    float* oF = outF + (size_t)z * outStride;
                    if (mA < M) oF[(size_t)mA * HW + p] = acc[mt][nt][e] + bvA;
                    if (mB < M) oF[(size_t)mB * HW + p] = acc[mt][nt][2 + e] + bvB;
                }
            }
        }
    }
}

// ======================= small kernels =======================
__global__ void wsplit_kernel(const float* __restrict__ src, bf16* __restrict__ h,
                              bf16* __restrict__ l, int M, int Mp)
{
    const int idx = blockIdx.x * blockDim.x + threadIdx.x;
    if (idx >= Mp * KTOT) return;
    const float v = (idx / KTOT < M) ? src[idx] : 0.f;
    const bf16 hh = __float2bfloat16(v);
    h[idx] = hh;
    l[idx] = __float2bfloat16(v - __bfloat162float(hh));
}

// tap-major weight split: dst k = tap*256 + c  <-  src k = c*9 + tap
__global__ void wsplit_tap_kernel(const float* __restrict__ src, bf16* __restrict__ h,
                                  bf16* __restrict__ l, int M, int Mp)
{
    const int idx = blockIdx.x * blockDim.x + threadIdx.x;
    if (idx >= Mp * KTOT) return;
    const int m = idx / KTOT, kk = idx % KTOT;
    const int t = kk >> 8, c = kk & 255;
    const float v = (m < M) ? src[(size_t)m * KTOT + c * 9 + t] : 0.f;
    const bf16 hh = __float2bfloat16(v);
    h[idx] = hh;
    l[idx] = __float2bfloat16(v - __bfloat162float(hh));
}

// x (fp32, p-domain) -> bf16 hi/lo, 112-padded rows, 3 shifted copies, 2 chains
__global__ void xsplit3_kernel(const float* __restrict__ x, bf16* __restrict__ oh, bf16* __restrict__ ol)
{
    const int idx = blockIdx.x * blockDim.x + threadIdx.x;
    if (idx >= 2 * 256 * NPIX) return;
    const int p2 = idx % NPIX;
    const int ch = idx / NPIX;            // chain*256 + c, chains = batches
    const int xq = p2 % 112, yq = p2 / 112;
    if (xq >= 100) return;
    const float v = x[(size_t)ch * HW + yq * 100 + xq];
    const bf16 h = __float2bfloat16(v);
    const bf16 l = __float2bfloat16(v - __bfloat162float(h));
    const size_t cb = (size_t)ch * CH112;
#pragma unroll
    for (int j = 0; j < 3; j++) {
        const int q = p2 - (j - 1);
        if (q >= 0) {
            const size_t o = (size_t)j * FC2 + cb + q;
            oh[o] = h;
            ol[o] = l;
        }
    }
}

// deform gather: reads bf16 hi/lo features (copy0 region, 112-padded), writes transposed col hi/lo
__global__ __launch_bounds__(256) void im2col_def_bf16(
    const bf16* __restrict__ fH, const bf16* __restrict__ fL, int t,
    const float* __restrict__ boxreg,
    bf16* __restrict__ ch, bf16* __restrict__ cl, int zoff)
{
    const int zl = blockIdx.y;
    const int z = zl + zoff;
    const int bpp = z / 9, ap = z % 9;
    const int nn = ap * 2 + bpp, bb = nn / 9, aa = nn % 9;
    const float aw = c_AW[aa], ah_ = c_AH[aa];
    const int idx = blockIdx.x * 256 + threadIdx.x;
    if (idx >= NPAD * 32) return;
    const int p = idx % NPAD, cblk = idx / NPAD;
    bf16* oh = ch + (size_t)zl * CSTR + (size_t)p * KTOT + cblk * 72;
    bf16* ol = cl + (size_t)zl * CSTR + (size_t)p * KTOT + cblk * 72;
    if (p >= HW) {
        const uint4 zz = make_uint4(0, 0, 0, 0);
#pragma unroll
        for (int g = 0; g < 9; g++) { *(uint4*)(oh + g * 8) = zz; *(uint4*)(ol + g * 8) = zz; }
        return;
    }
    const int chain = bpp * 2 + t;
    const bf16* fh0 = fH + (size_t)(chain * 256) * CH112;
    const bf16* fl0 = fL + (size_t)(chain * 256) * CH112;
    const float* br = boxreg + (size_t)bb * 36 * HW + (size_t)aa * 4 * HW + p;
    const int y = p / WID, x = p % WID;
    const float r0 = br[0], r1 = br[HW], r2 = br[2 * HW], r3 = br[3 * HW];
    const float whx = aw * expf(r2), why = ah_ * expf(r3);
    const float tlx = aw * r0 - 0.5f * whx, tly = ah_ * r1 - 0.5f * why;
    const float gxv[3] = {tlx, tlx + 0.5f * whx, tlx + whx};
    const float gyv[3] = {tly, tly + 0.5f * why, tly + why};
    int O00[9], O01[9], O10[9], O11[9];
    float W00[9], W01[9], W10[9], W11[9];
#pragma unroll
    for (int i = 0; i < 3; i++) {
        const float pxf = (float)x + gyv[i];
        const float x0f = floorf(pxf);
        const float lx = pxf - x0f;
        const int ix0 = (int)x0f;
        const bool vx0 = (ix0 >= 0) && (ix0 < WID), vx1 = (ix0 + 1 >= 0) && (ix0 + 1 < WID);
        const int xc0 = min(max(ix0, 0), WID - 1), xc1 = min(max(ix0 + 1, 0), WID - 1);
#pragma unroll
        for (int j = 0; j < 3; j++) {
            const int k = i * 3 + j;
            const float pyf = (float)y + gxv[j];
            const float y0f = floorf(pyf);
            const float ly = pyf - y0f;
            const int iy0 = (int)y0f;
            const bool vy0 = (iy0 >= 0) && (iy0 < WID), vy1 = (iy0 + 1 >= 0) && (iy0 + 1 < WID);
            const int yc0 = min(max(iy0, 0), WID - 1), yc1 = min(max(iy0 + 1, 0), WID - 1);
            O00[k] = yc0 * 112 + xc0; O01[k] = yc0 * 112 + xc1;
            O10[k] = yc1 * 112 + xc0; O11[k] = yc1 * 112 + xc1;
            W00[k] = (vy0 && vx0) ? (1.f - ly) * (1.f - lx) : 0.f;
            W01[k] = (vy0 && vx1) ? (1.f - ly) * lx : 0.f;
            W10[k] = (vy1 && vx0) ? ly * (1.f - lx) : 0.f;
            W11[k] = (vy1 && vx1) ? ly * lx : 0.f;
        }
    }
#pragma unroll 1
    for (int g = 0; g < 9; g++) {
        bf16 hs[8], ls[8];
#pragma unroll
        for (int j = 0; j < 8; j++) {
            const int e = g * 8 + j, cc = e / 9, k = e - cc * 9;
            const size_t co = (size_t)(cblk * 8 + cc) * CH112;
            const bf16* fh = fh0 + co;
            const bf16* fl = fl0 + co;
            const float v =
                W00[k] * (__bfloat162float(fh[O00[k]]) + __bfloat162float(fl[O00[k]])) +
                W01[k] * (__bfloat162float(fh[O01[k]]) + __bfloat162float(fl[O01[k]])) +
                W10[k] * (__bfloat162float(fh[O10[k]]) + __bfloat162float(fl[O10[k]])) +
                W11[k] * (__bfloat162float(fh[O11[k]]) + __bfloat162float(fl[O11[k]]));
            hs[j] = __float2bfloat16(v);
            ls[j] = __float2bfloat16(v - __bfloat162float(hs[j]));
        }
        *(uint4*)(oh + g * 8) = make_uint4(bpack(hs[0],hs[1]), bpack(hs[2],hs[3]),
                                           bpack(hs[4],hs[5]), bpack(hs[6],hs[7]));
        *(uint4*)(ol + g * 8) = make_uint4(bpack(ls[0],ls[1]), bpack(ls[2],ls[3]),
                                           bpack(ls[4],ls[5]), bpack(ls[6],ls[7]));
    }
}

__global__ void delta_kernel(const float* __restrict__ boxreg, const float* __restrict__ refine,
                             float* __restrict__ out)
{
    const int idx = blockIdx.x * blockDim.x + threadIdx.x;
    if (idx >= 2 * 36 * HW) return;
    const int p = idx % HW, ch = (idx / HW) % 36, b = idx / (36 * HW), c = ch & 3;
    const float o1 = boxreg[((size_t)b * 36 + ch) * HW + p];
    const float o2 = refine[((size_t)b * 36 + ch) * HW + p];
    float v;
    if (c < 2) v = o1 + expf(boxreg[((size_t)b * 36 + ch + 2) * HW + p]) * o2;
    else       v = o1 + o2;
    out[idx] = v;
}

#define W_CLS   0
#define W_REG   1024
#define W_PRED  2048
#define W_DCLS  2176
#define W_DREG  2432
#define W_LOGIT 2688
#define W_REFIN 3456

static cudaStream_t s_gather = nullptr;
static cudaEvent_t s_evG[12], s_evM[12], s_evFork, s_evJoin;
static void ensure_streams() {
    if (!s_gather) {
        cudaStreamCreateWithFlags(&s_gather, cudaStreamNonBlocking);
        for (int i = 0; i < 12; i++) {
            cudaEventCreateWithFlags(&s_evG[i], cudaEventDisableTiming);
            cudaEventCreateWithFlags(&s_evM[i], cudaEventDisableTiming);
        }
        cudaEventCreateWithFlags(&s_evFork, cudaEventDisableTiming);
        cudaEventCreateWithFlags(&s_evJoin, cudaEventDisableTiming);
    }
}

#define NT_CONV 88   // ceil(11200/128)

extern "C" void kernel_launch(void* const* d_in, const int* in_sizes, int n_in,
                              void* d_out, int out_size)
{
    const float* x        = (const float*)d_in[0];
    const float* cls_w    = (const float*)d_in[1];
    const float* cls_b    = (const float*)d_in[2];
    const float* reg_w    = (const float*)d_in[3];
    const float* reg_b    = (const float*)d_in[4];
    const float* pred_w   = (const float*)d_in[5];
    const float* pred_b   = (const float*)d_in[6];
    const float* dcls_w   = (const float*)d_in[7];
    const float* dreg_w   = (const float*)d_in[8];
    const float* logit_w  = (const float*)d_in[9];
    const float* logit_b  = (const float*)d_in[10];
    const float* refine_w = (const float*)d_in[11];
    const float* refine_b = (const float*)d_in[12];

    bf16 *wh, *wl, *colh, *coll, *cth, *ctl, *crh, *crl, *xh, *xl, *fAh, *fAl, *fBh, *fBl;
    float *boxreg, *refine;
    cudaGetSymbolAddress((void**)&wh, g_wh);
    cudaGetSymbolAddress((void**)&wl, g_wl);
    cudaGetSymbolAddress((void**)&colh, g_colh);
    cudaGetSymbolAddress((void**)&coll, g_coll);
    cudaGetSymbolAddress((void**)&cth, g_cth);
    cudaGetSymbolAddress((void**)&ctl, g_ctl);
    cudaGetSymbolAddress((void**)&crh, g_crh);
    cudaGetSymbolAddress((void**)&crl, g_crl);
    cudaGetSymbolAddress((void**)&xh, g_xh);
    cudaGetSymbolAddress((void**)&xl, g_xl);
    cudaGetSymbolAddress((void**)&fAh, g_fAh);
    cudaGetSymbolAddress((void**)&fAl, g_fAl);
    cudaGetSymbolAddress((void**)&fBh, g_fBh);
    cudaGetSymbolAddress((void**)&fBl, g_fBl);
    cudaGetSymbolAddress((void**)&boxreg, g_boxreg);
    cudaGetSymbolAddress((void**)&refine, g_refine);
    xh += FGUARD; xl += FGUARD;
    fAh += FGUARD; fAl += FGUARD; fBh += FGUARD; fBl += FGUARD;

    cudaFuncSetAttribute(mma_gemm, cudaFuncAttributeMaxDynamicSharedMemorySize, SMEM_SZ);
    cudaFuncSetAttribute(conv_gemm, cudaFuncAttributeMaxDynamicSharedMemorySize, SMEM_SZ);
    ensure_streams();

    // weight splits
    wsplit_tap_kernel<<<(1024 * KTOT + 255) / 256, 256>>>(cls_w, wh + (size_t)W_CLS * KTOT, wl + (size_t)W_CLS * KTOT, 1024, 1024);
    wsplit_tap_kernel<<<(1024 * KTOT + 255) / 256, 256>>>(reg_w, wh + (size_t)W_REG * KTOT, wl + (size_t)W_REG * KTOT, 1024, 1024);
    wsplit_tap_kernel<<<(128 * KTOT + 255) / 256, 256>>>(pred_w, wh + (size_t)W_PRED * KTOT, wl + (size_t)W_PRED * KTOT, 36, 128);
    wsplit_kernel<<<(256 * KTOT + 255) / 256, 256>>>(dcls_w, wh + (size_t)W_DCLS * KTOT, wl + (size_t)W_DCLS * KTOT, 256, 256);
    wsplit_kernel<<<(256 * KTOT + 255) / 256, 256>>>(dreg_w, wh + (size_t)W_DREG * KTOT, wl + (size_t)W_DREG * KTOT, 256, 256);
    wsplit_kernel<<<(768 * KTOT + 255) / 256, 256>>>(logit_w, wh + (size_t)W_LOGIT * KTOT, wl + (size_t)W_LOGIT * KTOT, 720, 768);
    wsplit_kernel<<<(128 * KTOT + 255) / 256, 256>>>(refine_w, wh + (size_t)W_REFIN * KTOT, wl + (size_t)W_REFIN * KTOT, 36, 128);

    // x -> padded shifted bf16 copies
    xsplit3_kernel<<<(2 * 256 * NPIX + 255) / 256, 256>>>(x, xh, xl);

    // ---- towers: 4 implicit conv layers, z = b*2 + tower ----
    // L0: x(2ch) -> fA ; L1: fA -> fB ; L2: fB -> fA ; L3: fA -> fB
    struct { const bf16 *ih, *il; size_t istr; int cshift; bf16 *oh, *ol; } L[4] = {
        {xh, xl, FC2, 1, fAh, fAl},
        {fAh, fAl, FC4, 0, fBh, fBl},
        {fBh, fBl, FC4, 0, fAh, fAl},
        {fAh, fAl, FC4, 0, fBh, fBl}};
    for (int layer = 0; layer < 4; layer++) {
        dim3 grid(NT_CONV, 2, 4);
        conv_gemm<<<grid, 256, SMEM_SZ>>>(
            wh, wl, W_CLS + layer * 256, W_REG + layer * 256,
            L[layer].ih, L[layer].il, L[layer].istr, 1, 0, L[layer].cshift,
            cls_b + layer * 256, reg_b + layer * 256,
            nullptr, 0, L[layer].oh, L[layer].ol, 256, 1 | 2 | 8 | 16);
    }

    // ---- pred conv: input rf chains (fB chains 1,3), fp32 out p-domain ----
    {
        dim3 grid(NT_CONV, 1, 2);
        conv_gemm<<<grid, 256, SMEM_SZ>>>(
            wh, wl, W_PRED, W_PRED,
            fBh, fBl, FC4, 2, 1, 0,
            pred_b, pred_b,
            boxreg, (size_t)36 * HW, nullptr, nullptr, 36, 1 | 32);
    }

    const bf16* f0h = fBh + FC4;   // copy index 1 = dx 0
    const bf16* f0l = fBl + FC4;

    // ---- deform: 12 pipelined phases (3 slots each), gathers on side stream ----
    {
        cudaEventRecord(s_evFork, 0);
        cudaStreamWaitEvent(s_gather, s_evFork, 0);
        const dim3 icg3(NPAD * 32 / 256, 3);
        const dim3 grid(NPAD / 128, 2, 3);
        for (int i = 0; i < 12; i++) {
            const int t = i / 6;
            const int base = (i % 6) * 3;
            const int half = (i & 1) * 3;
            bf16* bh = colh + (size_t)half * CSTR;
            bf16* bl = coll + (size_t)half * CSTR;
            if (i >= 2) cudaStreamWaitEvent(s_gather, s_evM[i - 2], 0);
            im2col_def_bf16<<<icg3, 256, 0, s_gather>>>(f0h, f0l, t, boxreg, bh, bl, base);
            cudaEventRecord(s_evG[i], s_gather);
            cudaStreamWaitEvent(0, s_evG[i], 0);
            mma_gemm<<<grid, 256, SMEM_SZ>>>(
                wh, wl, t == 0 ? W_DCLS : W_DREG, t == 0 ? W_DCLS : W_DREG,
                bh, bl, nullptr, nullptr, nullptr, 0,
                t == 0 ? cth : crh, t == 0 ? ctl : crl, 256, 4, base);
            cudaEventRecord(s_evM[i], 0);
        }
        cudaEventRecord(s_evJoin, s_gather);
        cudaStreamWaitEvent(0, s_evJoin, 0);
    }

    // ---- 1x1 heads ----
    float* logits_out = (float*)d_out;
    float* delta_out = logits_out + (size_t)2 * 720 * HW;
    {
        dim3 gl(NPAD / 128, 6, 2);
        mma_gemm<<<gl, 256, SMEM_SZ>>>(
            wh, wl, W_LOGIT, W_LOGIT, cth, ctl, logit_b, logit_b,
            logits_out, (size_t)720 * HW, nullptr, nullptr, 720, 1, 0);
        dim3 gr(NPAD / 128, 1, 2);
        mma_gemm<<<gr, 256, SMEM_SZ>>>(
            wh, wl, W_REFIN, W_REFIN, crh, crl, refine_b, refine_b,
            refine, (size_t)36 * HW, nullptr, nullptr, 36, 1, 0);
    }

    delta_kernel<<<(2 * 36 * HW + 255) / 256, 256>>>(boxreg, refine, delta_out);
}

// round 13
// speedup vs baseline: 1.4678x; 1.1696x over previous
#include <cuda_runtime.h>
#include <cuda_bf16.h>
#include <cstdint>
#include <cstddef>

#define HW    10000
#define WID   100
#define NPAD  10240
#define KTOT  2304
#define WROWS 3584
#define SLOTS 6
#define CSTR  ((size_t)NPAD * KTOT)
#define CH112 11312
#define NPIX  11200
#define FC4   ((size_t)4 * 256 * CH112)
#define FC2   ((size_t)2 * 256 * CH112)
#define FGUARD 128

typedef __nv_bfloat16 bf16;

__device__ bf16 g_wh[WROWS * KTOT];
__device__ bf16 g_wl[WROWS * KTOT];
__device__ bf16 g_colh[SLOTS * CSTR];
__device__ bf16 g_coll[SLOTS * CSTR];
__device__ bf16 g_cth[2 * CSTR];
__device__ bf16 g_ctl[2 * CSTR];
__device__ bf16 g_crh[2 * CSTR];
__device__ bf16 g_crl[2 * CSTR];
__device__ bf16 g_xh[FGUARD + 3 * FC2 + 256];
__device__ bf16 g_xl[FGUARD + 3 * FC2 + 256];
__device__ bf16 g_fAh[FGUARD + 3 * FC4 + 256];
__device__ bf16 g_fAl[FGUARD + 3 * FC4 + 256];
__device__ bf16 g_fBh[FGUARD + 3 * FC4 + 256];
__device__ bf16 g_fBl[FGUARD + 3 * FC4 + 256];
__device__ float g_f32[(size_t)4 * 256 * CH112];   // fp32 final-feature copy for gather (46MB)
__device__ float g_boxreg[2 * 36 * HW];
__device__ float g_refine[2 * 36 * HW];

__constant__ float c_AW[9] = {
    2.8284271247461903f, 2.0f, 1.4142135623730951f,
    3.5635948725613580f, 2.5198420997897464f, 1.7817974362806790f,
    4.4898481932374910f, 3.1748021039363988f, 2.2449240966187455f};
__constant__ float c_AH[9] = {
    1.4142135623730951f, 2.0f, 2.8284271247461903f,
    1.7817974362806790f, 2.5198420997897464f, 3.5635948725613580f,
    2.2449240966187455f, 3.1748021039363988f, 4.4898481932374910f};
__constant__ int c_dy9[9]   = {-1,-1,-1, 0,0,0, 1,1,1};
__constant__ int c_dxsel[9] = { 0, 1, 2, 0,1,2, 0,1,2};

__device__ __forceinline__ uint32_t smem_u32(const void* p) {
    uint32_t a;
    asm("{ .reg .u64 t; cvta.to.shared.u64 t, %1; cvt.u32.u64 %0, t; }" : "=r"(a) : "l"(p));
    return a;
}
__device__ __forceinline__ void cp16(uint32_t dst, const void* src) {
    asm volatile("cp.async.cg.shared.global [%0], [%1], 16;" :: "r"(dst), "l"(src));
}
__device__ __forceinline__ void ldmx4(uint32_t* r, uint32_t addr) {
    asm volatile("ldmatrix.sync.aligned.m8n8.x4.shared.b16 {%0,%1,%2,%3}, [%4];"
                 : "=r"(r[0]), "=r"(r[1]), "=r"(r[2]), "=r"(r[3]) : "r"(addr));
}
__device__ __forceinline__ void ldmx4t(uint32_t* r, uint32_t addr) {
    asm volatile("ldmatrix.sync.aligned.m8n8.x4.trans.shared.b16 {%0,%1,%2,%3}, [%4];"
                 : "=r"(r[0]), "=r"(r[1]), "=r"(r[2]), "=r"(r[3]) : "r"(addr));
}
__device__ __forceinline__ void mma16816(float* c, const uint32_t* a, uint32_t b0, uint32_t b1) {
    asm volatile("mma.sync.aligned.m16n8k16.row.col.f32.bf16.bf16.f32 "
                 "{%0,%1,%2,%3}, {%4,%5,%6,%7}, {%8,%9}, {%0,%1,%2,%3};"
                 : "+f"(c[0]), "+f"(c[1]), "+f"(c[2]), "+f"(c[3])
                 : "r"(a[0]), "r"(a[1]), "r"(a[2]), "r"(a[3]), "r"(b0), "r"(b1));
}
__device__ __forceinline__ uint32_t bpack(bf16 a, bf16 b) {
    return (uint32_t)__bfloat16_as_ushort(a) | ((uint32_t)__bfloat16_as_ushort(b) << 16);
}
__device__ __forceinline__ uint32_t sw_off(int r, int c) {
    return (uint32_t)((r * 4 + (c ^ (r & 3))) << 4);
}
__device__ __forceinline__ uint32_t swb_off(int r, int c) {
    return (uint32_t)((r * 16 + (c ^ (r & 7))) << 4);
}

#define TILE_B 8192
#define STAGE_B (4 * TILE_B)
#define NSTG 3
#define NK   72
#define SMEM_SZ (NSTG * STAGE_B)

// ============ explicit-col GEMM (deform + heads) ============
// flags: 1=bias 2=relu 4=cat-out 8=z-parity A/bias
__global__ __launch_bounds__(256, 2) void mma_gemm(
    const bf16* __restrict__ Ah0, const bf16* __restrict__ Al0, int arowE, int arowO,
    const bf16* __restrict__ Bh0, const bf16* __restrict__ Bl0,
    const float* __restrict__ biasE, const float* __restrict__ biasO,
    float* __restrict__ outF, size_t outStride,
    bf16* __restrict__ outTh, bf16* __restrict__ outTl,
    int M, int flags, int zoff)
{
    extern __shared__ char smem[];
    const uint32_t sb = smem_u32(smem);
    const int tid = threadIdx.x, lane = tid & 31, w = tid >> 5;
    const int wm = w >> 2, wn = w & 3;
    const int m0 = blockIdx.y * 128, n0 = blockIdx.x * 128;
    const int zl = blockIdx.z;
    const int z = zl + zoff;

    const bool odd = (flags & 8) && (z & 1);
    const int arow = odd ? arowO : arowE;
    const float* bias = odd ? biasO : biasE;

    const bf16* srcs[4] = {
        Ah0 + ((size_t)arow + m0) * KTOT, Al0 + ((size_t)arow + m0) * KTOT,
        Bh0 + (size_t)zl * CSTR + (size_t)n0 * KTOT,
        Bl0 + (size_t)zl * CSTR + (size_t)n0 * KTOT};

    float acc[4][4][4];
#pragma unroll
    for (int i = 0; i < 4; i++)
#pragma unroll
        for (int j = 0; j < 4; j++)
#pragma unroll
            for (int q = 0; q < 4; q++) acc[i][j][q] = 0.f;

    const int ra = (lane & 15);
    const int ca = lane >> 4;
    const int rb = (lane & 7) + ((lane >> 4) << 3);
    const int cb = (lane >> 3) & 1;

#define LOAD_STAGE(s, k0) do { \
    _Pragma("unroll") \
    for (int t = 0; t < 4; t++) { \
        const uint32_t base = sb + (uint32_t)((s) * STAGE_B + t * TILE_B); \
        _Pragma("unroll") \
        for (int h = 0; h < 2; h++) { \
            const int q = tid + h * 256; \
            const int r = q >> 2, c = q & 3; \
            cp16(base + sw_off(r, c), srcs[t] + (size_t)r * KTOT + (k0) + c * 8); \
        } \
    } \
} while (0)

    LOAD_STAGE(0, 0);
    asm volatile("cp.async.commit_group;" ::: "memory");
    LOAD_STAGE(1, 32);
    asm volatile("cp.async.commit_group;" ::: "memory");

    for (int kc = 0; kc < NK; kc++) {
        asm volatile("cp.async.wait_group 1;" ::: "memory");
        __syncthreads();
        const uint32_t bA  = sb + (uint32_t)((kc % NSTG) * STAGE_B);
        const uint32_t bAl = bA + TILE_B;
        const uint32_t bBh = bA + 2 * TILE_B;
        const uint32_t bBl = bA + 3 * TILE_B;
#pragma unroll
        for (int kh = 0; kh < 2; kh++) {
            uint32_t fbh[2][4], fbl[2][4];
#pragma unroll
            for (int nt2 = 0; nt2 < 2; nt2++) {
                const int rr = wn * 32 + nt2 * 16 + rb;
                const int cc = kh * 2 + cb;
                ldmx4(fbh[nt2], bBh + sw_off(rr, cc));
                ldmx4(fbl[nt2], bBl + sw_off(rr, cc));
            }
#pragma unroll
            for (int mt = 0; mt < 4; mt++) {
                uint32_t fah[4], fal[4];
                const int rr = wm * 64 + mt * 16 + ra;
                const int cc = kh * 2 + ca;
                ldmx4(fah, bA  + sw_off(rr, cc));
                ldmx4(fal, bAl + sw_off(rr, cc));
#pragma unroll
                for (int nt = 0; nt < 4; nt++) {
                    const uint32_t b0h = fbh[nt >> 1][(nt & 1) * 2];
                    const uint32_t b1h = fbh[nt >> 1][(nt & 1) * 2 + 1];
                    const uint32_t b0l = fbl[nt >> 1][(nt & 1) * 2];
                    const uint32_t b1l = fbl[nt >> 1][(nt & 1) * 2 + 1];
                    mma16816(acc[mt][nt], fah, b0h, b1h);
                    mma16816(acc[mt][nt], fah, b0l, b1l);
                    mma16816(acc[mt][nt], fal, b0h, b1h);
                }
            }
        }
        if (kc + 2 < NK) LOAD_STAGE((kc + 2) % NSTG, (kc + 2) * 32);
        asm volatile("cp.async.commit_group;" ::: "memory");
    }
    __syncthreads();
#undef LOAD_STAGE

    const int group = lane >> 2, tid4 = lane & 3;
    if (flags & 4) {
        const int bpp = z / 9, ap = z % 9;
        float* smf = (float*)smem;
#pragma unroll
        for (int mt = 0; mt < 4; mt++)
#pragma unroll
            for (int nt = 0; nt < 4; nt++) {
                const int ml = wm * 64 + mt * 16 + group;
                const int nl = wn * 32 + nt * 8 + tid4 * 2;
                smf[nl * 128 + ml]           = acc[mt][nt][0];
                smf[(nl + 1) * 128 + ml]     = acc[mt][nt][1];
                smf[nl * 128 + ml + 8]       = acc[mt][nt][2];
                smf[(nl + 1) * 128 + ml + 8] = acc[mt][nt][3];
            }
        __syncthreads();
        const int nl = tid >> 1, half = tid & 1;
        const size_t row_out = (size_t)(bpp * NPAD + n0 + nl) * KTOT + ap * 256 + m0 + half * 64;
        const float* row = smf + nl * 128 + half * 64;
        bf16* oh = outTh + row_out;
        bf16* ol = outTl + row_out;
#pragma unroll
        for (int g = 0; g < 8; g++) {
            bf16 hs[8], ls[8];
#pragma unroll
            for (int j = 0; j < 8; j++) {
                const float v = fmaxf(row[g * 8 + j], 0.f);
                hs[j] = __float2bfloat16(v);
                ls[j] = __float2bfloat16(v - __bfloat162float(hs[j]));
            }
            *(uint4*)(oh + g * 8) = make_uint4(bpack(hs[0],hs[1]), bpack(hs[2],hs[3]),
                                               bpack(hs[4],hs[5]), bpack(hs[6],hs[7]));
            *(uint4*)(ol + g * 8) = make_uint4(bpack(ls[0],ls[1]), bpack(ls[2],ls[3]),
                                               bpack(ls[4],ls[5]), bpack(ls[6],ls[7]));
        }
    } else {
        float* oF = outF + (size_t)z * outStride;
#pragma unroll
        for (int mt = 0; mt < 4; mt++) {
            const int mA = m0 + wm * 64 + mt * 16 + group;
            const int mB = mA + 8;
            const float bvA = ((flags & 1) && mA < M) ? bias[mA] : 0.f;
            const float bvB = ((flags & 1) && mB < M) ? bias[mB] : 0.f;
#pragma unroll
            for (int nt = 0; nt < 4; nt++) {
                const int n = n0 + wn * 32 + nt * 8 + tid4 * 2;
#pragma unroll
                for (int e = 0; e < 2; e++) {
                    if (n + e < HW) {
                        if (mA < M) {
                            float v = acc[mt][nt][e] + bvA;
                            if (flags & 2) v = fmaxf(v, 0.f);
                            oF[(size_t)mA * HW + n + e] = v;
                        }
                        if (mB < M) {
                            float v = acc[mt][nt][2 + e] + bvB;
                            if (flags & 2) v = fmaxf(v, 0.f);
                            oF[(size_t)mB * HW + n + e] = v;
                        }
                    }
                }
            }
        }
    }
}

// ============ implicit conv GEMM (towers + pred) ============
// flags: 1=bias 2=relu 8=z-parity 16=feat-out 32=fp32-p-out 64=also write fp32 feature copy
__global__ __launch_bounds__(256, 2) void conv_gemm(
    const bf16* __restrict__ Ah0, const bf16* __restrict__ Al0, int arowE, int arowO,
    const bf16* __restrict__ fInH, const bf16* __restrict__ fInL,
    size_t inCopyStr, int cmul, int cadd, int cshift,
    const float* __restrict__ biasE, const float* __restrict__ biasO,
    float* __restrict__ outF, size_t outStride,
    bf16* __restrict__ oFh, bf16* __restrict__ oFl,
    float* __restrict__ oF32,
    int M, int flags)
{
    extern __shared__ char smem[];
    const uint32_t sb = smem_u32(smem);
    const int tid = threadIdx.x, lane = tid & 31, w = tid >> 5;
    const int wm = w >> 2, wn = w & 3;
    const int m0 = blockIdx.y * 128, n0 = blockIdx.x * 128;
    const int z = blockIdx.z;
    const int inChain = ((z * cmul) + cadd) >> cshift;

    const bool odd = (flags & 8) && (z & 1);
    const int arow = odd ? arowO : arowE;
    const float* bias = odd ? biasO : biasE;

    const bf16* srcA[2] = {Ah0 + ((size_t)arow + m0) * KTOT, Al0 + ((size_t)arow + m0) * KTOT};
    const bf16* fbase[2] = {fInH + (size_t)inChain * 256 * CH112 + n0,
                            fInL + (size_t)inChain * 256 * CH112 + n0};

    float acc[4][4][4];
#pragma unroll
    for (int i = 0; i < 4; i++)
#pragma unroll
        for (int j = 0; j < 4; j++)
#pragma unroll
            for (int q = 0; q < 4; q++) acc[i][j][q] = 0.f;

    const int ra = (lane & 15);
    const int ca = lane >> 4;

#define LOAD_CSTAGE(s, kc) do { \
    const int _t = (kc) >> 3, _c0 = ((kc) & 7) << 5; \
    const long _toff = (long)c_dxsel[_t] * (long)inCopyStr + (long)c_dy9[_t] * 112; \
    _Pragma("unroll") \
    for (int t2 = 0; t2 < 2; t2++) { \
        const uint32_t baseA = sb + (uint32_t)((s) * STAGE_B + t2 * TILE_B); \
        _Pragma("unroll") \
        for (int h = 0; h < 2; h++) { \
            const int q = tid + h * 256; \
            const int r = q >> 2, c = q & 3; \
            cp16(baseA + sw_off(r, c), srcA[t2] + (size_t)r * KTOT + (kc) * 32 + c * 8); \
        } \
    } \
    _Pragma("unroll") \
    for (int t2 = 0; t2 < 2; t2++) { \
        const uint32_t baseB = sb + (uint32_t)((s) * STAGE_B + (2 + t2) * TILE_B); \
        _Pragma("unroll") \
        for (int h = 0; h < 2; h++) { \
            const int q = tid + h * 256; \
            const int r = q >> 4, c = q & 15; \
            cp16(baseB + swb_off(r, c), fbase[t2] + _toff + (size_t)(_c0 + r) * CH112 + c * 8); \
        } \
    } \
} while (0)

    LOAD_CSTAGE(0, 0);
    asm volatile("cp.async.commit_group;" ::: "memory");
    LOAD_CSTAGE(1, 1);
    asm volatile("cp.async.commit_group;" ::: "memory");

    for (int kc = 0; kc < NK; kc++) {
        asm volatile("cp.async.wait_group 1;" ::: "memory");
        __syncthreads();
        const uint32_t bA  = sb + (uint32_t)((kc % NSTG) * STAGE_B);
        const uint32_t bAl = bA + TILE_B;
        const uint32_t bBh = bA + 2 * TILE_B;
        const uint32_t bBl = bA + 3 * TILE_B;
#pragma unroll
        for (int kh = 0; kh < 2; kh++) {
            const int rowl = kh * 16 + (lane & 15);
            uint32_t fbh[2][4], fbl[2][4];
#pragma unroll
            for (int nt2 = 0; nt2 < 2; nt2++) {
                const int chunk = wn * 4 + nt2 * 2 + (lane >> 4);
                const uint32_t off = swb_off(rowl, chunk);
                ldmx4t(fbh[nt2], bBh + off);
                ldmx4t(fbl[nt2], bBl + off);
            }
#pragma unroll
            for (int mt = 0; mt < 4; mt++) {
                uint32_t fah[4], fal[4];
                const int rr = wm * 64 + mt * 16 + ra;
                const int cc = kh * 2 + ca;
                ldmx4(fah, bA  + sw_off(rr, cc));
                ldmx4(fal, bAl + sw_off(rr, cc));
#pragma unroll
                for (int nt = 0; nt < 4; nt++) {
                    const uint32_t b0h = fbh[nt >> 1][(nt & 1) * 2];
                    const uint32_t b1h = fbh[nt >> 1][(nt & 1) * 2 + 1];
                    const uint32_t b0l = fbl[nt >> 1][(nt & 1) * 2];
                    const uint32_t b1l = fbl[nt >> 1][(nt & 1) * 2 + 1];
                    mma16816(acc[mt][nt], fah, b0h, b1h);
                    mma16816(acc[mt][nt], fah, b0l, b1l);
                    mma16816(acc[mt][nt], fal, b0h, b1h);
                }
            }
        }
        if (kc + 2 < NK) LOAD_CSTAGE((kc + 2) % NSTG, kc + 2);
        asm volatile("cp.async.commit_group;" ::: "memory");
    }
    __syncthreads();
#undef LOAD_CSTAGE

    const int group = lane >> 2, tid4 = lane & 3;
#pragma unroll
    for (int mt = 0; mt < 4; mt++) {
        const int mA = m0 + wm * 64 + mt * 16 + group;
        const int mB = mA + 8;
        const float bvA = ((flags & 1) && mA < M) ? bias[mA] : 0.f;
        const float bvB = ((flags & 1) && mB < M) ? bias[mB] : 0.f;
#pragma unroll
        for (int nt = 0; nt < 4; nt++) {
            const int n = n0 + wn * 32 + nt * 8 + tid4 * 2;
#pragma unroll
            for (int e = 0; e < 2; e++) {
                const int p2 = n + e;
                if (p2 >= NPIX) continue;
                const int xq = p2 % 112;
                if (xq >= 100) continue;
                if (flags & 16) {
#pragma unroll
                    for (int half = 0; half < 2; half++) {
                        const int m = half ? mB : mA;
                        float v = (half ? acc[mt][nt][2 + e] : acc[mt][nt][e]) + (half ? bvB : bvA);
                        v = fmaxf(v, 0.f);
                        const bf16 h = __float2bfloat16(v);
                        const bf16 l = __float2bfloat16(v - __bfloat162float(h));
                        const size_t cb = (size_t)(z * 256 + m) * CH112;
                        if (flags & 64) oF32[cb + p2] = v;
#pragma unroll
                        for (int j = 0; j < 3; j++) {
                            const int q = p2 - (j - 1);
                            if (q >= 0) {
                                const size_t o = (size_t)j * FC4 + cb + q;
                                oFh[o] = h;
                                oFl[o] = l;
                            }
                        }
                    }
                } else {
                    const int p = (p2 / 112) * 100 + xq;
                    float* oF = outF + (size_t)z * outStride;
                    if (mA < M) oF[(size_t)mA * HW + p] = acc[mt][nt][e] + bvA;
                    if (mB < M) oF[(size_t)mB * HW + p] = acc[mt][nt][2 + e] + bvB;
                }
            }
        }
    }
}

// ============ small kernels ============
__global__ void wsplit_kernel(const float* __restrict__ src, bf16* __restrict__ h,
                              bf16* __restrict__ l, int M, int Mp)
{
    const int idx = blockIdx.x * blockDim.x + threadIdx.x;
    if (idx >= Mp * KTOT) return;
    const float v = (idx / KTOT < M) ? src[idx] : 0.f;
    const bf16 hh = __float2bfloat16(v);
    h[idx] = hh;
    l[idx] = __float2bfloat16(v - __bfloat162float(hh));
}

__global__ void wsplit_tap_kernel(const float* __restrict__ src, bf16* __restrict__ h,
                                  bf16* __restrict__ l, int M, int Mp)
{
    const int idx = blockIdx.x * blockDim.x + threadIdx.x;
    if (idx >= Mp * KTOT) return;
    const int m = idx / KTOT, kk = idx % KTOT;
    const int t = kk >> 8, c = kk & 255;
    const float v = (m < M) ? src[(size_t)m * KTOT + c * 9 + t] : 0.f;
    const bf16 hh = __float2bfloat16(v);
    h[idx] = hh;
    l[idx] = __float2bfloat16(v - __bfloat162float(hh));
}

__global__ void xsplit3_kernel(const float* __restrict__ x, bf16* __restrict__ oh, bf16* __restrict__ ol)
{
    const int idx = blockIdx.x * blockDim.x + threadIdx.x;
    if (idx >= 2 * 256 * NPIX) return;
    const int p2 = idx % NPIX;
    const int ch = idx / NPIX;
    const int xq = p2 % 112, yq = p2 / 112;
    if (xq >= 100) return;
    const float v = x[(size_t)ch * HW + yq * 100 + xq];
    const bf16 h = __float2bfloat16(v);
    const bf16 l = __float2bfloat16(v - __bfloat162float(h));
    const size_t cb = (size_t)ch * CH112;
#pragma unroll
    for (int j = 0; j < 3; j++) {
        const int q = p2 - (j - 1);
        if (q >= 0) {
            const size_t o = (size_t)j * FC2 + cb + q;
            oh[o] = h;
            ol[o] = l;
        }
    }
}

// deform gather from fp32 feature copy (112-padded), writes transposed col hi/lo
__global__ __launch_bounds__(256) void im2col_def_bf16(
    const float* __restrict__ f32, int t,
    const float* __restrict__ boxreg,
    bf16* __restrict__ ch, bf16* __restrict__ cl, int zoff)
{
    const int zl = blockIdx.y;
    const int z = zl + zoff;
    const int bpp = z / 9, ap = z % 9;
    const int nn = ap * 2 + bpp, bb = nn / 9, aa = nn % 9;
    const float aw = c_AW[aa], ah_ = c_AH[aa];
    const int idx = blockIdx.x * 256 + threadIdx.x;
    if (idx >= NPAD * 32) return;
    const int p = idx % NPAD, cblk = idx / NPAD;
    bf16* oh = ch + (size_t)zl * CSTR + (size_t)p * KTOT + cblk * 72;
    bf16* ol = cl + (size_t)zl * CSTR + (size_t)p * KTOT + cblk * 72;
    if (p >= HW) {
        const uint4 zz = make_uint4(0, 0, 0, 0);
#pragma unroll
        for (int g = 0; g < 9; g++) { *(uint4*)(oh + g * 8) = zz; *(uint4*)(ol + g * 8) = zz; }
        return;
    }
    const int chain = bpp * 2 + t;
    const float* f0 = f32 + (size_t)(chain * 256) * CH112;
    const float* br = boxreg + (size_t)bb * 36 * HW + (size_t)aa * 4 * HW + p;
    const int y = p / WID, x = p % WID;
    const float r0 = br[0], r1 = br[HW], r2 = br[2 * HW], r3 = br[3 * HW];
    const float whx = aw * expf(r2), why = ah_ * expf(r3);
    const float tlx = aw * r0 - 0.5f * whx, tly = ah_ * r1 - 0.5f * why;
    const float gxv[3] = {tlx, tlx + 0.5f * whx, tlx + whx};
    const float gyv[3] = {tly, tly + 0.5f * why, tly + why};
    int O00[9], O01[9], O10[9], O11[9];
    float W00[9], W01[9], W10[9], W11[9];
#pragma unroll
    for (int i = 0; i < 3; i++) {
        const float pxf = (float)x + gyv[i];
        const float x0f = floorf(pxf);
        const float lx = pxf - x0f;
        const int ix0 = (int)x0f;
        const bool vx0 = (ix0 >= 0) && (ix0 < WID), vx1 = (ix0 + 1 >= 0) && (ix0 + 1 < WID);
        const int xc0 = min(max(ix0, 0), WID - 1), xc1 = min(max(ix0 + 1, 0), WID - 1);
#pragma unroll
        for (int j = 0; j < 3; j++) {
            const int k = i * 3 + j;
            const float pyf = (float)y + gxv[j];
            const float y0f = floorf(pyf);
            const float ly = pyf - y0f;
            const int iy0 = (int)y0f;
            const bool vy0 = (iy0 >= 0) && (iy0 < WID), vy1 = (iy0 + 1 >= 0) && (iy0 + 1 < WID);
            const int yc0 = min(max(iy0, 0), WID - 1), yc1 = min(max(iy0 + 1, 0), WID - 1);
            O00[k] = yc0 * 112 + xc0; O01[k] = yc0 * 112 + xc1;
            O10[k] = yc1 * 112 + xc0; O11[k] = yc1 * 112 + xc1;
            W00[k] = (vy0 && vx0) ? (1.f - ly) * (1.f - lx) : 0.f;
            W01[k] = (vy0 && vx1) ? (1.f - ly) * lx : 0.f;
            W10[k] = (vy1 && vx0) ? ly * (1.f - lx) : 0.f;
            W11[k] = (vy1 && vx1) ? ly * lx : 0.f;
        }
    }
#pragma unroll 1
    for (int g = 0; g < 9; g++) {
        bf16 hs[8], ls[8];
#pragma unroll
        for (int j = 0; j < 8; j++) {
            const int e = g * 8 + j, cc = e / 9, k = e - cc * 9;
            const float* f = f0 + (size_t)(cblk * 8 + cc) * CH112;
            const float v = W00[k]*f[O00[k]] + W01[k]*f[O01[k]] + W10[k]*f[O10[k]] + W11[k]*f[O11[k]];
            hs[j] = __float2bfloat16(v);
            ls[j] = __float2bfloat16(v - __bfloat162float(hs[j]));
        }
        *(uint4*)(oh + g * 8) = make_uint4(bpack(hs[0],hs[1]), bpack(hs[2],hs[3]),
                                           bpack(hs[4],hs[5]), bpack(hs[6],hs[7]));
        *(uint4*)(ol + g * 8) = make_uint4(bpack(ls[0],ls[1]), bpack(ls[2],ls[3]),
                                           bpack(ls[4],ls[5]), bpack(ls[6],ls[7]));
    }
}

__global__ void delta_kernel(const float* __restrict__ boxreg, const float* __restrict__ refine,
                             float* __restrict__ out)
{
    const int idx = blockIdx.x * blockDim.x + threadIdx.x;
    if (idx >= 2 * 36 * HW) return;
    const int p = idx % HW, ch = (idx / HW) % 36, b = idx / (36 * HW), c = ch & 3;
    const float o1 = boxreg[((size_t)b * 36 + ch) * HW + p];
    const float o2 = refine[((size_t)b * 36 + ch) * HW + p];
    float v;
    if (c < 2) v = o1 + expf(boxreg[((size_t)b * 36 + ch + 2) * HW + p]) * o2;
    else       v = o1 + o2;
    out[idx] = v;
}

#define W_CLS   0
#define W_REG   1024
#define W_PRED  2048
#define W_DCLS  2176
#define W_DREG  2432
#define W_LOGIT 2688
#define W_REFIN 3456

static cudaStream_t s_gather = nullptr;
static cudaEvent_t s_evG[12], s_evM[12], s_evFork, s_evJoin;
static void ensure_streams() {
    if (!s_gather) {
        cudaStreamCreateWithFlags(&s_gather, cudaStreamNonBlocking);
        for (int i = 0; i < 12; i++) {
            cudaEventCreateWithFlags(&s_evG[i], cudaEventDisableTiming);
            cudaEventCreateWithFlags(&s_evM[i], cudaEventDisableTiming);
        }
        cudaEventCreateWithFlags(&s_evFork, cudaEventDisableTiming);
        cudaEventCreateWithFlags(&s_evJoin, cudaEventDisableTiming);
    }
}

#define NT_CONV 88

extern "C" void kernel_launch(void* const* d_in, const int* in_sizes, int n_in,
                              void* d_out, int out_size)
{
    const float* x        = (const float*)d_in[0];
    const float* cls_w    = (const float*)d_in[1];
    const float* cls_b    = (const float*)d_in[2];
    const float* reg_w    = (const float*)d_in[3];
    const float* reg_b    = (const float*)d_in[4];
    const float* pred_w   = (const float*)d_in[5];
    const float* pred_b   = (const float*)d_in[6];
    const float* dcls_w   = (const float*)d_in[7];
    const float* dreg_w   = (const float*)d_in[8];
    const float* logit_w  = (const float*)d_in[9];
    const float* logit_b  = (const float*)d_in[10];
    const float* refine_w = (const float*)d_in[11];
    const float* refine_b = (const float*)d_in[12];

    bf16 *wh, *wl, *colh, *coll, *cth, *ctl, *crh, *crl, *xh, *xl, *fAh, *fAl, *fBh, *fBl;
    float *f32, *boxreg, *refine;
    cudaGetSymbolAddress((void**)&wh, g_wh);
    cudaGetSymbolAddress((void**)&wl, g_wl);
    cudaGetSymbolAddress((void**)&colh, g_colh);
    cudaGetSymbolAddress((void**)&coll, g_coll);
    cudaGetSymbolAddress((void**)&cth, g_cth);
    cudaGetSymbolAddress((void**)&ctl, g_ctl);
    cudaGetSymbolAddress((void**)&crh, g_crh);
    cudaGetSymbolAddress((void**)&crl, g_crl);
    cudaGetSymbolAddress((void**)&xh, g_xh);
    cudaGetSymbolAddress((void**)&xl, g_xl);
    cudaGetSymbolAddress((void**)&fAh, g_fAh);
    cudaGetSymbolAddress((void**)&fAl, g_fAl);
    cudaGetSymbolAddress((void**)&fBh, g_fBh);
    cudaGetSymbolAddress((void**)&fBl, g_fBl);
    cudaGetSymbolAddress((void**)&f32, g_f32);
    cudaGetSymbolAddress((void**)&boxreg, g_boxreg);
    cudaGetSymbolAddress((void**)&refine, g_refine);
    xh += FGUARD; xl += FGUARD;
    fAh += FGUARD; fAl += FGUARD; fBh += FGUARD; fBl += FGUARD;

    cudaFuncSetAttribute(mma_gemm, cudaFuncAttributeMaxDynamicSharedMemorySize, SMEM_SZ);
    cudaFuncSetAttribute(conv_gemm, cudaFuncAttributeMaxDynamicSharedMemorySize, SMEM_SZ);
    ensure_streams();

    // ours #0-#2, so ours #3 (conv L0) lands at ncu's sample point
    wsplit_tap_kernel<<<(1024 * KTOT + 255) / 256, 256>>>(cls_w, wh + (size_t)W_CLS * KTOT, wl + (size_t)W_CLS * KTOT, 1024, 1024);
    wsplit_tap_kernel<<<(1024 * KTOT + 255) / 256, 256>>>(reg_w, wh + (size_t)W_REG * KTOT, wl + (size_t)W_REG * KTOT, 1024, 1024);
    xsplit3_kernel<<<(2 * 256 * NPIX + 255) / 256, 256>>>(x, xh, xl);

    // ---- towers: 4 implicit conv layers, z = b*2 + tower ----
    struct { const bf16 *ih, *il; size_t istr; int cshift; bf16 *oh, *ol; int xf; } L[4] = {
        {xh, xl, FC2, 1, fAh, fAl, 0},
        {fAh, fAl, FC4, 0, fBh, fBl, 0},
        {fBh, fBl, FC4, 0, fAh, fAl, 0},
        {fAh, fAl, FC4, 0, fBh, fBl, 64}};   // L3 also writes fp32 copy
    for (int layer = 0; layer < 4; layer++) {
        dim3 grid(NT_CONV, 2, 4);
        conv_gemm<<<grid, 256, SMEM_SZ>>>(
            wh, wl, W_CLS + layer * 256, W_REG + layer * 256,
            L[layer].ih, L[layer].il, L[layer].istr, 1, 0, L[layer].cshift,
            cls_b + layer * 256, reg_b + layer * 256,
            nullptr, 0, L[layer].oh, L[layer].ol, f32,
            256, 1 | 2 | 8 | 16 | L[layer].xf);
    }

    // remaining weight splits
    wsplit_tap_kernel<<<(128 * KTOT + 255) / 256, 256>>>(pred_w, wh + (size_t)W_PRED * KTOT, wl + (size_t)W_PRED * KTOT, 36, 128);
    wsplit_kernel<<<(256 * KTOT + 255) / 256, 256>>>(dcls_w, wh + (size_t)W_DCLS * KTOT, wl + (size_t)W_DCLS * KTOT, 256, 256);
    wsplit_kernel<<<(256 * KTOT + 255) / 256, 256>>>(dreg_w, wh + (size_t)W_DREG * KTOT, wl + (size_t)W_DREG * KTOT, 256, 256);
    wsplit_kernel<<<(768 * KTOT + 255) / 256, 256>>>(logit_w, wh + (size_t)W_LOGIT * KTOT, wl + (size_t)W_LOGIT * KTOT, 720, 768);
    wsplit_kernel<<<(128 * KTOT + 255) / 256, 256>>>(refine_w, wh + (size_t)W_REFIN * KTOT, wl + (size_t)W_REFIN * KTOT, 36, 128);

    // ---- pred conv (rf chains = fB chains 1,3) ----
    {
        dim3 grid(NT_CONV, 1, 2);
        conv_gemm<<<grid, 256, SMEM_SZ>>>(
            wh, wl, W_PRED, W_PRED,
            fBh, fBl, FC4, 2, 1, 0,
            pred_b, pred_b,
            boxreg, (size_t)36 * HW, nullptr, nullptr, nullptr, 36, 1 | 32);
    }

    // ---- deform: 12 pipelined phases, gathers on side stream (fp32 source) ----
    {
        cudaEventRecord(s_evFork, 0);
        cudaStreamWaitEvent(s_gather, s_evFork, 0);
        const dim3 icg3(NPAD * 32 / 256, 3);
        const dim3 grid(NPAD / 128, 2, 3);
        for (int i = 0; i < 12; i++) {
            const int t = i / 6;
            const int base = (i % 6) * 3;
            const int half = (i & 1) * 3;
            bf16* bh = colh + (size_t)half * CSTR;
            bf16* bl = coll + (size_t)half * CSTR;
            if (i >= 2) cudaStreamWaitEvent(s_gather, s_evM[i - 2], 0);
            im2col_def_bf16<<<icg3, 256, 0, s_gather>>>(f32, t, boxreg, bh, bl, base);
            cudaEventRecord(s_evG[i], s_gather);
            cudaStreamWaitEvent(0, s_evG[i], 0);
            mma_gemm<<<grid, 256, SMEM_SZ>>>(
                wh, wl, t == 0 ? W_DCLS : W_DREG, t == 0 ? W_DCLS : W_DREG,
                bh, bl, nullptr, nullptr, nullptr, 0,
                t == 0 ? cth : crh, t == 0 ? ctl : crl, 256, 4, base);
            cudaEventRecord(s_evM[i], 0);
        }
        cudaEventRecord(s_evJoin, s_gather);
        cudaStreamWaitEvent(0, s_evJoin, 0);
    }

    // ---- 1x1 heads ----
    float* logits_out = (float*)d_out;
    float* delta_out = logits_out + (size_t)2 * 720 * HW;
    {
        dim3 gl(NPAD / 128, 6, 2);
        mma_gemm<<<gl, 256, SMEM_SZ>>>(
            wh, wl, W_LOGIT, W_LOGIT, cth, ctl, logit_b, logit_b,
            logits_out, (size_t)720 * HW, nullptr, nullptr, 720, 1, 0);
        dim3 gr(NPAD / 128, 1, 2);
        mma_gemm<<<gr, 256, SMEM_SZ>>>(
            wh, wl, W_REFIN, W_REFIN, crh, crl, refine_b, refine_b,
            refine, (size_t)36 * HW, nullptr, nullptr, 36, 1, 0);
    }

    delta_kernel<<<(2 * 36 * HW + 255) / 256, 256>>>(boxreg, refine, delta_out);
}

// round 14
// speedup vs baseline: 1.9431x; 1.3238x over previous
#include <cuda_runtime.h>
#include <cuda_bf16.h>
#include <cuda_fp16.h>
#include <cstdint>
#include <cstddef>

#define HW    10000
#define WID   100
#define NPAD  10240
#define KTOT  2304
#define WROWS 3072
#define CSTR  ((size_t)NPAD * KTOT)
#define CH112 11312
#define NPIX  11200
#define FC4   ((size_t)4 * 256 * CH112)
#define FGUARD 128

typedef __nv_bfloat16 bf16;

__device__ bf16 g_wh[WROWS * KTOT];                  // bf16 weights (towers/pred/heads)
__device__ bf16 g_wl[WROWS * KTOT];
__device__ __half g_wfh[512 * KTOT];                 // fp16 hi/lo deform weights (dcls:0, dreg:256)
__device__ __half g_wfl[512 * KTOT];
__device__ __half g_colf[12 * CSTR];                 // fp16 col, 12 slots (566 MB)
__device__ bf16 g_cth[2 * CSTR];                     // cat bf16 hi/lo
__device__ bf16 g_ctl[2 * CSTR];
__device__ bf16 g_crh[2 * CSTR];
__device__ bf16 g_crl[2 * CSTR];
__device__ bf16 g_fAh[FGUARD + 3 * FC4 + 256];
__device__ bf16 g_fAl[FGUARD + 3 * FC4 + 256];
__device__ bf16 g_fBh[FGUARD + 3 * FC4 + 256];       // also holds x (chains 0,1) before L1
__device__ bf16 g_fBl[FGUARD + 3 * FC4 + 256];
__device__ float g_f32[(size_t)4 * 256 * CH112];
__device__ float g_boxreg[2 * 36 * HW];
__device__ float g_refine[2 * 36 * HW];

__constant__ float c_AW[9] = {
    2.8284271247461903f, 2.0f, 1.4142135623730951f,
    3.5635948725613580f, 2.5198420997897464f, 1.7817974362806790f,
    4.4898481932374910f, 3.1748021039363988f, 2.2449240966187455f};
__constant__ float c_AH[9] = {
    1.4142135623730951f, 2.0f, 2.8284271247461903f,
    1.7817974362806790f, 2.5198420997897464f, 3.5635948725613580f,
    2.2449240966187455f, 3.1748021039363988f, 4.4898481932374910f};
__constant__ int c_dy9[9]   = {-1,-1,-1, 0,0,0, 1,1,1};
__constant__ int c_dxsel[9] = { 0, 1, 2, 0,1,2, 0,1,2};

__device__ __forceinline__ uint32_t smem_u32(const void* p) {
    uint32_t a;
    asm("{ .reg .u64 t; cvta.to.shared.u64 t, %1; cvt.u32.u64 %0, t; }" : "=r"(a) : "l"(p));
    return a;
}
__device__ __forceinline__ void cp16(uint32_t dst, const void* src) {
    asm volatile("cp.async.cg.shared.global [%0], [%1], 16;" :: "r"(dst), "l"(src));
}
__device__ __forceinline__ void ldmx4(uint32_t* r, uint32_t addr) {
    asm volatile("ldmatrix.sync.aligned.m8n8.x4.shared.b16 {%0,%1,%2,%3}, [%4];"
                 : "=r"(r[0]), "=r"(r[1]), "=r"(r[2]), "=r"(r[3]) : "r"(addr));
}
__device__ __forceinline__ void ldmx4t(uint32_t* r, uint32_t addr) {
    asm volatile("ldmatrix.sync.aligned.m8n8.x4.trans.shared.b16 {%0,%1,%2,%3}, [%4];"
                 : "=r"(r[0]), "=r"(r[1]), "=r"(r[2]), "=r"(r[3]) : "r"(addr));
}
__device__ __forceinline__ void mma_bf(float* c, const uint32_t* a, uint32_t b0, uint32_t b1) {
    asm volatile("mma.sync.aligned.m16n8k16.row.col.f32.bf16.bf16.f32 "
                 "{%0,%1,%2,%3}, {%4,%5,%6,%7}, {%8,%9}, {%0,%1,%2,%3};"
                 : "+f"(c[0]), "+f"(c[1]), "+f"(c[2]), "+f"(c[3])
                 : "r"(a[0]), "r"(a[1]), "r"(a[2]), "r"(a[3]), "r"(b0), "r"(b1));
}
__device__ __forceinline__ void mma_hf(float* c, const uint32_t* a, uint32_t b0, uint32_t b1) {
    asm volatile("mma.sync.aligned.m16n8k16.row.col.f32.f16.f16.f32 "
                 "{%0,%1,%2,%3}, {%4,%5,%6,%7}, {%8,%9}, {%0,%1,%2,%3};"
                 : "+f"(c[0]), "+f"(c[1]), "+f"(c[2]), "+f"(c[3])
                 : "r"(a[0]), "r"(a[1]), "r"(a[2]), "r"(a[3]), "r"(b0), "r"(b1));
}
__device__ __forceinline__ uint32_t bpack(bf16 a, bf16 b) {
    return (uint32_t)__bfloat16_as_ushort(a) | ((uint32_t)__bfloat16_as_ushort(b) << 16);
}
__device__ __forceinline__ uint32_t hpack(__half a, __half b) {
    return (uint32_t)__half_as_ushort(a) | ((uint32_t)__half_as_ushort(b) << 16);
}
__device__ __forceinline__ uint32_t sw_off(int r, int c) {
    return (uint32_t)((r * 4 + (c ^ (r & 3))) << 4);
}
__device__ __forceinline__ uint32_t swb_off(int r, int c) {
    return (uint32_t)((r * 16 + (c ^ (r & 7))) << 4);
}

#define TILE_B 8192
#define STAGE_B (4 * TILE_B)
#define NSTG 3
#define NK   72
#define SMEM_SZ (NSTG * STAGE_B)       // 96 KB (bf16 3-term kernels)
#define STAGE_F (3 * TILE_B)
#define SMEM_F (NSTG * STAGE_F)        // 72 KB (fp16 2-term kernel)

// ============ bf16 3-term GEMM (heads: logit / refine) ============
// flags: 1=bias
__global__ __launch_bounds__(256, 2) void mma_gemm(
    const bf16* __restrict__ Ah0, const bf16* __restrict__ Al0, int arow,
    const bf16* __restrict__ Bh0, const bf16* __restrict__ Bl0,
    const float* __restrict__ bias,
    float* __restrict__ outF, size_t outStride, int M, int flags)
{
    extern __shared__ char smem[];
    const uint32_t sb = smem_u32(smem);
    const int tid = threadIdx.x, lane = tid & 31, w = tid >> 5;
    const int wm = w >> 2, wn = w & 3;
    const int m0 = blockIdx.y * 128, n0 = blockIdx.x * 128;
    const int z = blockIdx.z;

    const bf16* srcs[4] = {
        Ah0 + ((size_t)arow + m0) * KTOT, Al0 + ((size_t)arow + m0) * KTOT,
        Bh0 + (size_t)z * CSTR + (size_t)n0 * KTOT,
        Bl0 + (size_t)z * CSTR + (size_t)n0 * KTOT};

    float acc[4][4][4];
#pragma unroll
    for (int i = 0; i < 4; i++)
#pragma unroll
        for (int j = 0; j < 4; j++)
#pragma unroll
            for (int q = 0; q < 4; q++) acc[i][j][q] = 0.f;

    const int ra = (lane & 15);
    const int ca = lane >> 4;
    const int rb = (lane & 7) + ((lane >> 4) << 3);
    const int cb = (lane >> 3) & 1;

#define LOAD_STAGE(s, k0) do { \
    _Pragma("unroll") \
    for (int t = 0; t < 4; t++) { \
        const uint32_t base = sb + (uint32_t)((s) * STAGE_B + t * TILE_B); \
        _Pragma("unroll") \
        for (int h = 0; h < 2; h++) { \
            const int q = tid + h * 256; \
            const int r = q >> 2, c = q & 3; \
            cp16(base + sw_off(r, c), srcs[t] + (size_t)r * KTOT + (k0) + c * 8); \
        } \
    } \
} while (0)

    LOAD_STAGE(0, 0);
    asm volatile("cp.async.commit_group;" ::: "memory");
    LOAD_STAGE(1, 32);
    asm volatile("cp.async.commit_group;" ::: "memory");

    for (int kc = 0; kc < NK; kc++) {
        asm volatile("cp.async.wait_group 1;" ::: "memory");
        __syncthreads();
        const uint32_t bA  = sb + (uint32_t)((kc % NSTG) * STAGE_B);
        const uint32_t bAl = bA + TILE_B;
        const uint32_t bBh = bA + 2 * TILE_B;
        const uint32_t bBl = bA + 3 * TILE_B;
#pragma unroll
        for (int kh = 0; kh < 2; kh++) {
            uint32_t fbh[2][4], fbl[2][4];
#pragma unroll
            for (int nt2 = 0; nt2 < 2; nt2++) {
                const int rr = wn * 32 + nt2 * 16 + rb;
                const int cc = kh * 2 + cb;
                ldmx4(fbh[nt2], bBh + sw_off(rr, cc));
                ldmx4(fbl[nt2], bBl + sw_off(rr, cc));
            }
#pragma unroll
            for (int mt = 0; mt < 4; mt++) {
                uint32_t fah[4], fal[4];
                const int rr = wm * 64 + mt * 16 + ra;
                const int cc = kh * 2 + ca;
                ldmx4(fah, bA  + sw_off(rr, cc));
                ldmx4(fal, bAl + sw_off(rr, cc));
#pragma unroll
                for (int nt = 0; nt < 4; nt++) {
                    const uint32_t b0h = fbh[nt >> 1][(nt & 1) * 2];
                    const uint32_t b1h = fbh[nt >> 1][(nt & 1) * 2 + 1];
                    const uint32_t b0l = fbl[nt >> 1][(nt & 1) * 2];
                    const uint32_t b1l = fbl[nt >> 1][(nt & 1) * 2 + 1];
                    mma_bf(acc[mt][nt], fah, b0h, b1h);
                    mma_bf(acc[mt][nt], fah, b0l, b1l);
                    mma_bf(acc[mt][nt], fal, b0h, b1h);
                }
            }
        }
        if (kc + 2 < NK) LOAD_STAGE((kc + 2) % NSTG, (kc + 2) * 32);
        asm volatile("cp.async.commit_group;" ::: "memory");
    }
    __syncthreads();
#undef LOAD_STAGE

    const int group = lane >> 2, tid4 = lane & 3;
    float* oF = outF + (size_t)z * outStride;
#pragma unroll
    for (int mt = 0; mt < 4; mt++) {
        const int mA = m0 + wm * 64 + mt * 16 + group;
        const int mB = mA + 8;
        const float bvA = ((flags & 1) && mA < M) ? bias[mA] : 0.f;
        const float bvB = ((flags & 1) && mB < M) ? bias[mB] : 0.f;
#pragma unroll
        for (int nt = 0; nt < 4; nt++) {
            const int n = n0 + wn * 32 + nt * 8 + tid4 * 2;
#pragma unroll
            for (int e = 0; e < 2; e++) {
                if (n + e < HW) {
                    if (mA < M) oF[(size_t)mA * HW + n + e] = acc[mt][nt][e] + bvA;
                    if (mB < M) oF[(size_t)mB * HW + n + e] = acc[mt][nt][2 + e] + bvB;
                }
            }
        }
    }
}

// ============ fp16 2-term GEMM (deform convs) ============
// z = 0..5: tower t=z&1 (0=cls,1=reg); deform index = base3 + (z>>1); cat epilogue.
__global__ __launch_bounds__(256, 2) void mma_gemm_f16(
    const __half* __restrict__ Wh, const __half* __restrict__ Wl,
    const __half* __restrict__ colBase,
    bf16* __restrict__ cth, bf16* __restrict__ ctl,
    bf16* __restrict__ crh, bf16* __restrict__ crl,
    int base3)
{
    extern __shared__ char smem[];
    const uint32_t sb = smem_u32(smem);
    const int tid = threadIdx.x, lane = tid & 31, w = tid >> 5;
    const int wm = w >> 2, wn = w & 3;
    const int m0 = blockIdx.y * 128, n0 = blockIdx.x * 128;
    const int z = blockIdx.z;
    const int t = z & 1;
    const int dIdx = base3 + (z >> 1);

    const __half* srcA[2] = {Wh + ((size_t)(t * 256) + m0) * KTOT,
                             Wl + ((size_t)(t * 256) + m0) * KTOT};
    const __half* srcB = colBase + (size_t)z * CSTR + (size_t)n0 * KTOT;

    float acc[4][4][4];
#pragma unroll
    for (int i = 0; i < 4; i++)
#pragma unroll
        for (int j = 0; j < 4; j++)
#pragma unroll
            for (int q = 0; q < 4; q++) acc[i][j][q] = 0.f;

    const int ra = (lane & 15);
    const int ca = lane >> 4;
    const int rb = (lane & 7) + ((lane >> 4) << 3);
    const int cb = (lane >> 3) & 1;

#define LOAD_FSTAGE(s, k0) do { \
    _Pragma("unroll") \
    for (int tt = 0; tt < 2; tt++) { \
        const uint32_t base = sb + (uint32_t)((s) * STAGE_F + tt * TILE_B); \
        _Pragma("unroll") \
        for (int h = 0; h < 2; h++) { \
            const int q = tid + h * 256; \
            const int r = q >> 2, c = q & 3; \
            cp16(base + sw_off(r, c), srcA[tt] + (size_t)r * KTOT + (k0) + c * 8); \
        } \
    } \
    { \
        const uint32_t base = sb + (uint32_t)((s) * STAGE_F + 2 * TILE_B); \
        _Pragma("unroll") \
        for (int h = 0; h < 2; h++) { \
            const int q = tid + h * 256; \
            const int r = q >> 2, c = q & 3; \
            cp16(base + sw_off(r, c), srcB + (size_t)r * KTOT + (k0) + c * 8); \
        } \
    } \
} while (0)

    LOAD_FSTAGE(0, 0);
    asm volatile("cp.async.commit_group;" ::: "memory");
    LOAD_FSTAGE(1, 32);
    asm volatile("cp.async.commit_group;" ::: "memory");

    for (int kc = 0; kc < NK; kc++) {
        asm volatile("cp.async.wait_group 1;" ::: "memory");
        __syncthreads();
        const uint32_t bA  = sb + (uint32_t)((kc % NSTG) * STAGE_F);
        const uint32_t bAl = bA + TILE_B;
        const uint32_t bB  = bA + 2 * TILE_B;
#pragma unroll
        for (int kh = 0; kh < 2; kh++) {
            uint32_t fb[2][4];
#pragma unroll
            for (int nt2 = 0; nt2 < 2; nt2++) {
                const int rr = wn * 32 + nt2 * 16 + rb;
                const int cc = kh * 2 + cb;
                ldmx4(fb[nt2], bB + sw_off(rr, cc));
            }
#pragma unroll
            for (int mt = 0; mt < 4; mt++) {
                uint32_t fah[4], fal[4];
                const int rr = wm * 64 + mt * 16 + ra;
                const int cc = kh * 2 + ca;
                ldmx4(fah, bA  + sw_off(rr, cc));
                ldmx4(fal, bAl + sw_off(rr, cc));
#pragma unroll
                for (int nt = 0; nt < 4; nt++) {
                    const uint32_t b0 = fb[nt >> 1][(nt & 1) * 2];
                    const uint32_t b1 = fb[nt >> 1][(nt & 1) * 2 + 1];
                    mma_hf(acc[mt][nt], fah, b0, b1);
                    mma_hf(acc[mt][nt], fal, b0, b1);
                }
            }
        }
        if (kc + 2 < NK) LOAD_FSTAGE((kc + 2) % NSTG, (kc + 2) * 32);
        asm volatile("cp.async.commit_group;" ::: "memory");
    }
    __syncthreads();
#undef LOAD_FSTAGE

    // cat epilogue: transpose through smem, write bf16 hi/lo
    const int group = lane >> 2, tid4 = lane & 3;
    const int bpp = dIdx / 9, ap = dIdx % 9;
    bf16* outTh = t ? crh : cth;
    bf16* outTl = t ? crl : ctl;
    float* smf = (float*)smem;
#pragma unroll
    for (int mt = 0; mt < 4; mt++)
#pragma unroll
        for (int nt = 0; nt < 4; nt++) {
            const int ml = wm * 64 + mt * 16 + group;
            const int nl = wn * 32 + nt * 8 + tid4 * 2;
            smf[nl * 128 + ml]           = acc[mt][nt][0];
            smf[(nl + 1) * 128 + ml]     = acc[mt][nt][1];
            smf[nl * 128 + ml + 8]       = acc[mt][nt][2];
            smf[(nl + 1) * 128 + ml + 8] = acc[mt][nt][3];
        }
    __syncthreads();
    const int nl = tid >> 1, half = tid & 1;
    const size_t row_out = (size_t)(bpp * NPAD + n0 + nl) * KTOT + ap * 256 + m0 + half * 64;
    const float* row = smf + nl * 128 + half * 64;
    bf16* oh = outTh + row_out;
    bf16* ol = outTl + row_out;
#pragma unroll
    for (int g = 0; g < 8; g++) {
        bf16 hs[8], ls[8];
#pragma unroll
        for (int j = 0; j < 8; j++) {
            const float v = fmaxf(row[g * 8 + j], 0.f);
            hs[j] = __float2bfloat16(v);
            ls[j] = __float2bfloat16(v - __bfloat162float(hs[j]));
        }
        *(uint4*)(oh + g * 8) = make_uint4(bpack(hs[0],hs[1]), bpack(hs[2],hs[3]),
                                           bpack(hs[4],hs[5]), bpack(hs[6],hs[7]));
        *(uint4*)(ol + g * 8) = make_uint4(bpack(ls[0],ls[1]), bpack(ls[2],ls[3]),
                                           bpack(ls[4],ls[5]), bpack(ls[6],ls[7]));
    }
}

// ============ implicit conv GEMM (towers + pred), unchanged R13 ============
// flags: 1=bias 2=relu 8=z-parity 16=feat-out 32=fp32-p-out 64=also write fp32 copy
__global__ __launch_bounds__(256, 2) void conv_gemm(
    const bf16* __restrict__ Ah0, const bf16* __restrict__ Al0, int arowE, int arowO,
    const bf16* __restrict__ fInH, const bf16* __restrict__ fInL,
    size_t inCopyStr, int cmul, int cadd, int cshift,
    const float* __restrict__ biasE, const float* __restrict__ biasO,
    float* __restrict__ outF, size_t outStride,
    bf16* __restrict__ oFh, bf16* __restrict__ oFl,
    float* __restrict__ oF32,
    int M, int flags)
{
    extern __shared__ char smem[];
    const uint32_t sb = smem_u32(smem);
    const int tid = threadIdx.x, lane = tid & 31, w = tid >> 5;
    const int wm = w >> 2, wn = w & 3;
    const int m0 = blockIdx.y * 128, n0 = blockIdx.x * 128;
    const int z = blockIdx.z;
    const int inChain = ((z * cmul) + cadd) >> cshift;

    const bool odd = (flags & 8) && (z & 1);
    const int arow = odd ? arowO : arowE;
    const float* bias = odd ? biasO : biasE;

    const bf16* srcA[2] = {Ah0 + ((size_t)arow + m0) * KTOT, Al0 + ((size_t)arow + m0) * KTOT};
    const bf16* fbase[2] = {fInH + (size_t)inChain * 256 * CH112 + n0,
                            fInL + (size_t)inChain * 256 * CH112 + n0};

    float acc[4][4][4];
#pragma unroll
    for (int i = 0; i < 4; i++)
#pragma unroll
        for (int j = 0; j < 4; j++)
#pragma unroll
            for (int q = 0; q < 4; q++) acc[i][j][q] = 0.f;

    const int ra = (lane & 15);
    const int ca = lane >> 4;

#define LOAD_CSTAGE(s, kc) do { \
    const int _t = (kc) >> 3, _c0 = ((kc) & 7) << 5; \
    const long _toff = (long)c_dxsel[_t] * (long)inCopyStr + (long)c_dy9[_t] * 112; \
    _Pragma("unroll") \
    for (int t2 = 0; t2 < 2; t2++) { \
        const uint32_t baseA = sb + (uint32_t)((s) * STAGE_B + t2 * TILE_B); \
        _Pragma("unroll") \
        for (int h = 0; h < 2; h++) { \
            const int q = tid + h * 256; \
            const int r = q >> 2, c = q & 3; \
            cp16(baseA + sw_off(r, c), srcA[t2] + (size_t)r * KTOT + (kc) * 32 + c * 8); \
        } \
    } \
    _Pragma("unroll") \
    for (int t2 = 0; t2 < 2; t2++) { \
        const uint32_t baseB = sb + (uint32_t)((s) * STAGE_B + (2 + t2) * TILE_B); \
        _Pragma("unroll") \
        for (int h = 0; h < 2; h++) { \
            const int q = tid + h * 256; \
            const int r = q >> 4, c = q & 15; \
            cp16(baseB + swb_off(r, c), fbase[t2] + _toff + (size_t)(_c0 + r) * CH112 + c * 8); \
        } \
    } \
} while (0)

    LOAD_CSTAGE(0, 0);
    asm volatile("cp.async.commit_group;" ::: "memory");
    LOAD_CSTAGE(1, 1);
    asm volatile("cp.async.commit_group;" ::: "memory");

    for (int kc = 0; kc < NK; kc++) {
        asm volatile("cp.async.wait_group 1;" ::: "memory");
        __syncthreads();
        const uint32_t bA  = sb + (uint32_t)((kc % NSTG) * STAGE_B);
        const uint32_t bAl = bA + TILE_B;
        const uint32_t bBh = bA + 2 * TILE_B;
        const uint32_t bBl = bA + 3 * TILE_B;
#pragma unroll
        for (int kh = 0; kh < 2; kh++) {
            const int rowl = kh * 16 + (lane & 15);
            uint32_t fbh[2][4], fbl[2][4];
#pragma unroll
            for (int nt2 = 0; nt2 < 2; nt2++) {
                const int chunk = wn * 4 + nt2 * 2 + (lane >> 4);
                const uint32_t off = swb_off(rowl, chunk);
                ldmx4t(fbh[nt2], bBh + off);
                ldmx4t(fbl[nt2], bBl + off);
            }
#pragma unroll
            for (int mt = 0; mt < 4; mt++) {
                uint32_t fah[4], fal[4];
                const int rr = wm * 64 + mt * 16 + ra;
                const int cc = kh * 2 + ca;
                ldmx4(fah, bA  + sw_off(rr, cc));
                ldmx4(fal, bAl + sw_off(rr, cc));
#pragma unroll
                for (int nt = 0; nt < 4; nt++) {
                    const uint32_t b0h = fbh[nt >> 1][(nt & 1) * 2];
                    const uint32_t b1h = fbh[nt >> 1][(nt & 1) * 2 + 1];
                    const uint32_t b0l = fbl[nt >> 1][(nt & 1) * 2];
                    const uint32_t b1l = fbl[nt >> 1][(nt & 1) * 2 + 1];
                    mma_bf(acc[mt][nt], fah, b0h, b1h);
                    mma_bf(acc[mt][nt], fah, b0l, b1l);
                    mma_bf(acc[mt][nt], fal, b0h, b1h);
                }
            }
        }
        if (kc + 2 < NK) LOAD_CSTAGE((kc + 2) % NSTG, kc + 2);
        asm volatile("cp.async.commit_group;" ::: "memory");
    }
    __syncthreads();
#undef LOAD_CSTAGE

    const int group = lane >> 2, tid4 = lane & 3;
#pragma unroll
    for (int mt = 0; mt < 4; mt++) {
        const int mA = m0 + wm * 64 + mt * 16 + group;
        const int mB = mA + 8;
        const float bvA = ((flags & 1) && mA < M) ? bias[mA] : 0.f;
        const float bvB = ((flags & 1) && mB < M) ? bias[mB] : 0.f;
#pragma unroll
        for (int nt = 0; nt < 4; nt++) {
            const int n = n0 + wn * 32 + nt * 8 + tid4 * 2;
#pragma unroll
            for (int e = 0; e < 2; e++) {
                const int p2 = n + e;
                if (p2 >= NPIX) continue;
                const int xq = p2 % 112;
                if (xq >= 100) continue;
                if (flags & 16) {
#pragma unroll
                    for (int half = 0; half < 2; half++) {
                        const int m = half ? mB : mA;
                        float v = (half ? acc[mt][nt][2 + e] : acc[mt][nt][e]) + (half ? bvB : bvA);
                        v = fmaxf(v, 0.f);
                        const bf16 h = __float2bfloat16(v);
                        const bf16 l = __float2bfloat16(v - __bfloat162float(h));
                        const size_t cb = (size_t)(z * 256 + m) * CH112;
                        if (flags & 64) oF32[cb + p2] = v;
#pragma unroll
                        for (int j = 0; j < 3; j++) {
                            const int q = p2 - (j - 1);
                            if (q >= 0) {
                                const size_t o = (size_t)j * FC4 + cb + q;
                                oFh[o] = h;
                                oFl[o] = l;
                            }
                        }
                    }
                } else {
                    const int p = (p2 / 112) * 100 + xq;
                    float* oF = outF + (size_t)z * outStride;
                    if (mA < M) oF[(size_t)mA * HW + p] = acc[mt][nt][e] + bvA;
                    if (mB < M) oF[(size_t)mB * HW + p] = acc[mt][nt][2 + e] + bvB;
                }
            }
        }
    }
}

// ============ small kernels ============
__global__ void wsplit_kernel(const float* __restrict__ src, bf16* __restrict__ h,
                              bf16* __restrict__ l, int M, int Mp)
{
    const int idx = blockIdx.x * blockDim.x + threadIdx.x;
    if (idx >= Mp * KTOT) return;
    const float v = (idx / KTOT < M) ? src[idx] : 0.f;
    const bf16 hh = __float2bfloat16(v);
    h[idx] = hh;
    l[idx] = __float2bfloat16(v - __bfloat162float(hh));
}

__global__ void wsplit_tap_kernel(const float* __restrict__ src, bf16* __restrict__ h,
                                  bf16* __restrict__ l, int M, int Mp)
{
    const int idx = blockIdx.x * blockDim.x + threadIdx.x;
    if (idx >= Mp * KTOT) return;
    const int m = idx / KTOT, kk = idx % KTOT;
    const int t = kk >> 8, c = kk & 255;
    const float v = (m < M) ? src[(size_t)m * KTOT + c * 9 + t] : 0.f;
    const bf16 hh = __float2bfloat16(v);
    h[idx] = hh;
    l[idx] = __float2bfloat16(v - __bfloat162float(hh));
}

__global__ void wsplit_f16_kernel(const float* __restrict__ src, __half* __restrict__ h,
                                  __half* __restrict__ l, int M)
{
    const int idx = blockIdx.x * blockDim.x + threadIdx.x;
    if (idx >= M * KTOT) return;
    const float v = src[idx];
    const __half hh = __float2half_rn(v);
    h[idx] = hh;
    l[idx] = __float2half_rn(v - __half2float(hh));
}

// x -> bf16 hi/lo 112-padded, 3 shifted copies, chains 0,1 of a 4-chain buffer
__global__ void xsplit3_kernel(const float* __restrict__ x, bf16* __restrict__ oh, bf16* __restrict__ ol)
{
    const int idx = blockIdx.x * blockDim.x + threadIdx.x;
    if (idx >= 2 * 256 * NPIX) return;
    const int p2 = idx % NPIX;
    const int ch = idx / NPIX;
    const int xq = p2 % 112, yq = p2 / 112;
    if (xq >= 100) return;
    const float v = x[(size_t)ch * HW + yq * 100 + xq];
    const bf16 h = __float2bfloat16(v);
    const bf16 l = __float2bfloat16(v - __bfloat162float(h));
    const size_t cb = (size_t)ch * CH112;
#pragma unroll
    for (int j = 0; j < 3; j++) {
        const int q = p2 - (j - 1);
        if (q >= 0) {
            const size_t o = (size_t)j * FC4 + cb + q;
            oh[o] = h;
            ol[o] = l;
        }
    }
}

// fused deform gather (cls + reg): fp32 source, fp16 col out, 6 slots per phase
__global__ __launch_bounds__(256) void im2col_def_f16(
    const float* __restrict__ f32, const float* __restrict__ boxreg,
    __half* __restrict__ colBase, int base3)
{
    const int zl = blockIdx.y;               // 0..2
    const int dIdx = base3 + zl;
    const int bpp = dIdx / 9, ap = dIdx % 9;
    const int nn = ap * 2 + bpp, bb = nn / 9, aa = nn % 9;
    const float aw = c_AW[aa], ah_ = c_AH[aa];
    const int idx = blockIdx.x * 256 + threadIdx.x;
    if (idx >= NPAD * 32) return;
    const int p = idx % NPAD, cblk = idx / NPAD;
    __half* o0 = colBase + (size_t)(zl * 2)     * CSTR + (size_t)p * KTOT + cblk * 72;
    __half* o1 = colBase + (size_t)(zl * 2 + 1) * CSTR + (size_t)p * KTOT + cblk * 72;
    if (p >= HW) {
        const uint4 zz = make_uint4(0, 0, 0, 0);
#pragma unroll
        for (int g = 0; g < 9; g++) { *(uint4*)(o0 + g * 8) = zz; *(uint4*)(o1 + g * 8) = zz; }
        return;
    }
    const float* br = boxreg + (size_t)bb * 36 * HW + (size_t)aa * 4 * HW + p;
    const int y = p / WID, x = p % WID;
    const float r0 = br[0], r1 = br[HW], r2 = br[2 * HW], r3 = br[3 * HW];
    const float whx = aw * expf(r2), why = ah_ * expf(r3);
    const float tlx = aw * r0 - 0.5f * whx, tly = ah_ * r1 - 0.5f * why;
    const float gxv[3] = {tlx, tlx + 0.5f * whx, tlx + whx};
    const float gyv[3] = {tly, tly + 0.5f * why, tly + why};
    int O00[9], O01[9], O10[9], O11[9];
    float W00[9], W01[9], W10[9], W11[9];
#pragma unroll
    for (int i = 0; i < 3; i++) {
        const float pxf = (float)x + gyv[i];
        const float x0f = floorf(pxf);
        const float lx = pxf - x0f;
        const int ix0 = (int)x0f;
        const bool vx0 = (ix0 >= 0) && (ix0 < WID), vx1 = (ix0 + 1 >= 0) && (ix0 + 1 < WID);
        const int xc0 = min(max(ix0, 0), WID - 1), xc1 = min(max(ix0 + 1, 0), WID - 1);
#pragma unroll
        for (int j = 0; j < 3; j++) {
            const int k = i * 3 + j;
            const float pyf = (float)y + gxv[j];
            const float y0f = floorf(pyf);
            const float ly = pyf - y0f;
            const int iy0 = (int)y0f;
            const bool vy0 = (iy0 >= 0) && (iy0 < WID), vy1 = (iy0 + 1 >= 0) && (iy0 + 1 < WID);
            const int yc0 = min(max(iy0, 0), WID - 1), yc1 = min(max(iy0 + 1, 0), WID - 1);
            O00[k] = yc0 * 112 + xc0; O01[k] = yc0 * 112 + xc1;
            O10[k] = yc1 * 112 + xc0; O11[k] = yc1 * 112 + xc1;
            W00[k] = (vy0 && vx0) ? (1.f - ly) * (1.f - lx) : 0.f;
            W01[k] = (vy0 && vx1) ? (1.f - ly) * lx : 0.f;
            W10[k] = (vy1 && vx0) ? ly * (1.f - lx) : 0.f;
            W11[k] = (vy1 && vx1) ? ly * lx : 0.f;
        }
    }
#pragma unroll
    for (int t = 0; t < 2; t++) {
        const float* f0 = f32 + (size_t)((bpp * 2 + t) * 256) * CH112;
        __half* out = t ? o1 : o0;
#pragma unroll 1
        for (int g = 0; g < 9; g++) {
            __half hs[8];
#pragma unroll
            for (int j = 0; j < 8; j++) {
                const int e = g * 8 + j, cc = e / 9, k = e - cc * 9;
                const float* f = f0 + (size_t)(cblk * 8 + cc) * CH112;
                const float v = W00[k]*f[O00[k]] + W01[k]*f[O01[k]] + W10[k]*f[O10[k]] + W11[k]*f[O11[k]];
                hs[j] = __float2half_rn(v);
            }
            *(uint4*)(out + g * 8) = make_uint4(hpack(hs[0],hs[1]), hpack(hs[2],hs[3]),
                                                hpack(hs[4],hs[5]), hpack(hs[6],hs[7]));
        }
    }
}

__global__ void delta_kernel(const float* __restrict__ boxreg, const float* __restrict__ refine,
                             float* __restrict__ out)
{
    const int idx = blockIdx.x * blockDim.x + threadIdx.x;
    if (idx >= 2 * 36 * HW) return;
    const int p = idx % HW, ch = (idx / HW) % 36, b = idx / (36 * HW), c = ch & 3;
    const float o1 = boxreg[((size_t)b * 36 + ch) * HW + p];
    const float o2 = refine[((size_t)b * 36 + ch) * HW + p];
    float v;
    if (c < 2) v = o1 + expf(boxreg[((size_t)b * 36 + ch + 2) * HW + p]) * o2;
    else       v = o1 + o2;
    out[idx] = v;
}

#define W_CLS   0
#define W_REG   1024
#define W_PRED  2048
#define W_LOGIT 2176
#define W_REFIN 2944

static cudaStream_t s_gather = nullptr;
static cudaEvent_t s_evG[6], s_evM[6], s_evFork, s_evJoin;
static void ensure_streams() {
    if (!s_gather) {
        cudaStreamCreateWithFlags(&s_gather, cudaStreamNonBlocking);
        for (int i = 0; i < 6; i++) {
            cudaEventCreateWithFlags(&s_evG[i], cudaEventDisableTiming);
            cudaEventCreateWithFlags(&s_evM[i], cudaEventDisableTiming);
        }
        cudaEventCreateWithFlags(&s_evFork, cudaEventDisableTiming);
        cudaEventCreateWithFlags(&s_evJoin, cudaEventDisableTiming);
    }
}

#define NT_CONV 88

extern "C" void kernel_launch(void* const* d_in, const int* in_sizes, int n_in,
                              void* d_out, int out_size)
{
    const float* x        = (const float*)d_in[0];
    const float* cls_w    = (const float*)d_in[1];
    const float* cls_b    = (const float*)d_in[2];
    const float* reg_w    = (const float*)d_in[3];
    const float* reg_b    = (const float*)d_in[4];
    const float* pred_w   = (const float*)d_in[5];
    const float* pred_b   = (const float*)d_in[6];
    const float* dcls_w   = (const float*)d_in[7];
    const float* dreg_w   = (const float*)d_in[8];
    const float* logit_w  = (const float*)d_in[9];
    const float* logit_b  = (const float*)d_in[10];
    const float* refine_w = (const float*)d_in[11];
    const float* refine_b = (const float*)d_in[12];

    bf16 *wh, *wl, *cth, *ctl, *crh, *crl, *fAh, *fAl, *fBh, *fBl;
    __half *wfh, *wfl, *colf;
    float *f32, *boxreg, *refine;
    cudaGetSymbolAddress((void**)&wh, g_wh);
    cudaGetSymbolAddress((void**)&wl, g_wl);
    cudaGetSymbolAddress((void**)&wfh, g_wfh);
    cudaGetSymbolAddress((void**)&wfl, g_wfl);
    cudaGetSymbolAddress((void**)&colf, g_colf);
    cudaGetSymbolAddress((void**)&cth, g_cth);
    cudaGetSymbolAddress((void**)&ctl, g_ctl);
    cudaGetSymbolAddress((void**)&crh, g_crh);
    cudaGetSymbolAddress((void**)&crl, g_crl);
    cudaGetSymbolAddress((void**)&fAh, g_fAh);
    cudaGetSymbolAddress((void**)&fAl, g_fAl);
    cudaGetSymbolAddress((void**)&fBh, g_fBh);
    cudaGetSymbolAddress((void**)&fBl, g_fBl);
    cudaGetSymbolAddress((void**)&f32, g_f32);
    cudaGetSymbolAddress((void**)&boxreg, g_boxreg);
    cudaGetSymbolAddress((void**)&refine, g_refine);
    fAh += FGUARD; fAl += FGUARD; fBh += FGUARD; fBl += FGUARD;

    cudaFuncSetAttribute(mma_gemm, cudaFuncAttributeMaxDynamicSharedMemorySize, SMEM_SZ);
    cudaFuncSetAttribute(conv_gemm, cudaFuncAttributeMaxDynamicSharedMemorySize, SMEM_SZ);
    cudaFuncSetAttribute(mma_gemm_f16, cudaFuncAttributeMaxDynamicSharedMemorySize, SMEM_F);
    ensure_streams();

    wsplit_tap_kernel<<<(1024 * KTOT + 255) / 256, 256>>>(cls_w, wh + (size_t)W_CLS * KTOT, wl + (size_t)W_CLS * KTOT, 1024, 1024);
    wsplit_tap_kernel<<<(1024 * KTOT + 255) / 256, 256>>>(reg_w, wh + (size_t)W_REG * KTOT, wl + (size_t)W_REG * KTOT, 1024, 1024);
    xsplit3_kernel<<<(2 * 256 * NPIX + 255) / 256, 256>>>(x, fBh, fBl);   // x staged in fB chains 0,1

    // ---- towers: L0 reads x (fB chains 0,1, cshift=1); L1 fA->fB; L2 fB->fA; L3 fA->fB (+f32) ----
    struct { const bf16 *ih, *il; int cshift; bf16 *oh, *ol; int xf; } L[4] = {
        {fBh, fBl, 1, fAh, fAl, 0},
        {fAh, fAl, 0, fBh, fBl, 0},
        {fBh, fBl, 0, fAh, fAl, 0},
        {fAh, fAl, 0, fBh, fBl, 64}};
    for (int layer = 0; layer < 4; layer++) {
        dim3 grid(NT_CONV, 2, 4);
        conv_gemm<<<grid, 256, SMEM_SZ>>>(
            wh, wl, W_CLS + layer * 256, W_REG + layer * 256,
            L[layer].ih, L[layer].il, FC4, 1, 0, L[layer].cshift,
            cls_b + layer * 256, reg_b + layer * 256,
            nullptr, 0, L[layer].oh, L[layer].ol, f32,
            256, 1 | 2 | 8 | 16 | L[layer].xf);
    }

    // remaining weight splits
    wsplit_tap_kernel<<<(128 * KTOT + 255) / 256, 256>>>(pred_w, wh + (size_t)W_PRED * KTOT, wl + (size_t)W_PRED * KTOT, 36, 128);
    wsplit_f16_kernel<<<(256 * KTOT + 255) / 256, 256>>>(dcls_w, wfh, wfl, 256);
    wsplit_f16_kernel<<<(256 * KTOT + 255) / 256, 256>>>(dreg_w, wfh + (size_t)256 * KTOT, wfl + (size_t)256 * KTOT, 256);
    wsplit_kernel<<<(768 * KTOT + 255) / 256, 256>>>(logit_w, wh + (size_t)W_LOGIT * KTOT, wl + (size_t)W_LOGIT * KTOT, 720, 768);
    wsplit_kernel<<<(128 * KTOT + 255) / 256, 256>>>(refine_w, wh + (size_t)W_REFIN * KTOT, wl + (size_t)W_REFIN * KTOT, 36, 128);

    // ---- pred conv (rf chains = fB chains 1,3) ----
    {
        dim3 grid(NT_CONV, 1, 2);
        conv_gemm<<<grid, 256, SMEM_SZ>>>(
            wh, wl, W_PRED, W_PRED,
            fBh, fBl, FC4, 2, 1, 0,
            pred_b, pred_b,
            boxreg, (size_t)36 * HW, nullptr, nullptr, nullptr, 36, 1 | 32);
    }

    // ---- deform: 6 fused phases (gather cls+reg on side stream; 6-z fp16 GEMM) ----
    {
        cudaEventRecord(s_evFork, 0);
        cudaStreamWaitEvent(s_gather, s_evFork, 0);
        const dim3 icg3(NPAD * 32 / 256, 3);
        const dim3 grid(NPAD / 128, 2, 6);
        for (int ph = 0; ph < 6; ph++) {
            const int base3 = ph * 3;
            __half* cb = colf + (size_t)(ph & 1) * 6 * CSTR;
            if (ph >= 2) cudaStreamWaitEvent(s_gather, s_evM[ph - 2], 0);
            im2col_def_f16<<<icg3, 256, 0, s_gather>>>(f32, boxreg, cb, base3);
            cudaEventRecord(s_evG[ph], s_gather);
            cudaStreamWaitEvent(0, s_evG[ph], 0);
            mma_gemm_f16<<<grid, 256, SMEM_F>>>(wfh, wfl, cb, cth, ctl, crh, crl, base3);
            cudaEventRecord(s_evM[ph], 0);
        }
        cudaEventRecord(s_evJoin, s_gather);
        cudaStreamWaitEvent(0, s_evJoin, 0);
    }

    // ---- 1x1 heads ----
    float* logits_out = (float*)d_out;
    float* delta_out = logits_out + (size_t)2 * 720 * HW;
    {
        dim3 gl(NPAD / 128, 6, 2);
        mma_gemm<<<gl, 256, SMEM_SZ>>>(
            wh, wl, W_LOGIT, cth, ctl, logit_b,
            logits_out, (size_t)720 * HW, 720, 1);
        dim3 gr(NPAD / 128, 1, 2);
        mma_gemm<<<gr, 256, SMEM_SZ>>>(
            wh, wl, W_REFIN, crh, crl, refine_b,
            refine, (size_t)36 * HW, 36, 1);
    }

    delta_kernel<<<(2 * 36 * HW + 255) / 256, 256>>>(boxreg, refine, delta_out);
}

// round 15
// speedup vs baseline: 2.1439x; 1.1034x over previous
#include <cuda_runtime.h>
#include <cuda_bf16.h>
#include <cuda_fp16.h>
#include <cstdint>
#include <cstddef>

#define HW    10000
#define WID   100
#define NPAD  10240
#define KTOT  2304
#define WROWS 3584
#define CSTR  ((size_t)NPAD * KTOT)
#define CH112 11312
#define NPIX  11200
#define FC4   ((size_t)4 * 256 * CH112)
#define FGUARD 128

__device__ __half g_wfh[WROWS * KTOT];               // fp16 hi weights (all layers)
__device__ __half g_wfl[WROWS * KTOT];               // fp16 lo weights
__device__ __half g_colf[12 * CSTR];                 // fp16 deform col, 12 slots
__device__ __half g_catc[2 * CSTR];                  // fp16 cls cat
__device__ __half g_catr[2 * CSTR];                  // fp16 reg cat
__device__ __half g_fA[FGUARD + 3 * FC4 + 256];      // fp16 features ping (3 shifted copies)
__device__ __half g_fB[FGUARD + 3 * FC4 + 256];      // fp16 features pong (x staged in chains 0,1)
__device__ float g_f32[(size_t)4 * 256 * CH112];     // fp32 final features for gather
__device__ float g_boxreg[2 * 36 * HW];
__device__ float g_refine[2 * 36 * HW];

__constant__ float c_AW[9] = {
    2.8284271247461903f, 2.0f, 1.4142135623730951f,
    3.5635948725613580f, 2.5198420997897464f, 1.7817974362806790f,
    4.4898481932374910f, 3.1748021039363988f, 2.2449240966187455f};
__constant__ float c_AH[9] = {
    1.4142135623730951f, 2.0f, 2.8284271247461903f,
    1.7817974362806790f, 2.5198420997897464f, 3.5635948725613580f,
    2.2449240966187455f, 3.1748021039363988f, 4.4898481932374910f};
__constant__ int c_dy9[9]   = {-1,-1,-1, 0,0,0, 1,1,1};
__constant__ int c_dxsel[9] = { 0, 1, 2, 0,1,2, 0,1,2};

__device__ __forceinline__ uint32_t smem_u32(const void* p) {
    uint32_t a;
    asm("{ .reg .u64 t; cvta.to.shared.u64 t, %1; cvt.u32.u64 %0, t; }" : "=r"(a) : "l"(p));
    return a;
}
__device__ __forceinline__ void cp16(uint32_t dst, const void* src) {
    asm volatile("cp.async.cg.shared.global [%0], [%1], 16;" :: "r"(dst), "l"(src));
}
__device__ __forceinline__ void ldmx4(uint32_t* r, uint32_t addr) {
    asm volatile("ldmatrix.sync.aligned.m8n8.x4.shared.b16 {%0,%1,%2,%3}, [%4];"
                 : "=r"(r[0]), "=r"(r[1]), "=r"(r[2]), "=r"(r[3]) : "r"(addr));
}
__device__ __forceinline__ void ldmx4t(uint32_t* r, uint32_t addr) {
    asm volatile("ldmatrix.sync.aligned.m8n8.x4.trans.shared.b16 {%0,%1,%2,%3}, [%4];"
                 : "=r"(r[0]), "=r"(r[1]), "=r"(r[2]), "=r"(r[3]) : "r"(addr));
}
__device__ __forceinline__ void mma_hf(float* c, const uint32_t* a, uint32_t b0, uint32_t b1) {
    asm volatile("mma.sync.aligned.m16n8k16.row.col.f32.f16.f16.f32 "
                 "{%0,%1,%2,%3}, {%4,%5,%6,%7}, {%8,%9}, {%0,%1,%2,%3};"
                 : "+f"(c[0]), "+f"(c[1]), "+f"(c[2]), "+f"(c[3])
                 : "r"(a[0]), "r"(a[1]), "r"(a[2]), "r"(a[3]), "r"(b0), "r"(b1));
}
__device__ __forceinline__ uint32_t hpack(__half a, __half b) {
    return (uint32_t)__half_as_ushort(a) | ((uint32_t)__half_as_ushort(b) << 16);
}
__device__ __forceinline__ uint32_t sw_off(int r, int c) {
    return (uint32_t)((r * 4 + (c ^ (r & 3))) << 4);
}
__device__ __forceinline__ uint32_t swb_off(int r, int c) {
    return (uint32_t)((r * 16 + (c ^ (r & 7))) << 4);
}

#define TILE_B 8192
#define NSTG 3
#define NK   72
#define STAGE_F (3 * TILE_B)
#define SMEM_F (NSTG * STAGE_F)   // 72 KB -> 2 CTAs/SM (also covers 64KB transpose scratch)

// ============ fp16 2-term GEMM, explicit B [rows, K] (deform + heads) ============
// flags: 1=bias(fp32 out)  4=cat-out  8=z-parity (deform: t=z&1 picks weights/cat)
__global__ __launch_bounds__(256, 2) void gemm_f16(
    const __half* __restrict__ Wh, const __half* __restrict__ Wl, int arowE, int arowO,
    const __half* __restrict__ Bbase,
    const float* __restrict__ bias,
    float* __restrict__ outF, size_t outStride,
    __half* __restrict__ catc, __half* __restrict__ catr,
    int M, int flags, int zoff)
{
    extern __shared__ char smem[];
    const uint32_t sb = smem_u32(smem);
    const int tid = threadIdx.x, lane = tid & 31, w = tid >> 5;
    const int wm = w >> 2, wn = w & 3;
    const int m0 = blockIdx.y * 128, n0 = blockIdx.x * 128;
    const int z = blockIdx.z;
    const int t = (flags & 8) ? (z & 1) : 0;
    const int arow = t ? arowO : arowE;

    const __half* srcA[2] = {Wh + ((size_t)arow + m0) * KTOT, Wl + ((size_t)arow + m0) * KTOT};
    const __half* srcB = Bbase + (size_t)z * CSTR + (size_t)n0 * KTOT;

    float acc[4][4][4];
#pragma unroll
    for (int i = 0; i < 4; i++)
#pragma unroll
        for (int j = 0; j < 4; j++)
#pragma unroll
            for (int q = 0; q < 4; q++) acc[i][j][q] = 0.f;

    const int ra = (lane & 15);
    const int ca = lane >> 4;
    const int rb = (lane & 7) + ((lane >> 4) << 3);
    const int cb = (lane >> 3) & 1;

#define LOAD_STAGE(s, k0) do { \
    _Pragma("unroll") \
    for (int tt = 0; tt < 2; tt++) { \
        const uint32_t base = sb + (uint32_t)((s) * STAGE_F + tt * TILE_B); \
        _Pragma("unroll") \
        for (int h = 0; h < 2; h++) { \
            const int q = tid + h * 256; \
            const int r = q >> 2, c = q & 3; \
            cp16(base + sw_off(r, c), srcA[tt] + (size_t)r * KTOT + (k0) + c * 8); \
        } \
    } \
    { \
        const uint32_t base = sb + (uint32_t)((s) * STAGE_F + 2 * TILE_B); \
        _Pragma("unroll") \
        for (int h = 0; h < 2; h++) { \
            const int q = tid + h * 256; \
            const int r = q >> 2, c = q & 3; \
            cp16(base + sw_off(r, c), srcB + (size_t)r * KTOT + (k0) + c * 8); \
        } \
    } \
} while (0)

    LOAD_STAGE(0, 0);
    asm volatile("cp.async.commit_group;" ::: "memory");
    LOAD_STAGE(1, 32);
    asm volatile("cp.async.commit_group;" ::: "memory");

    for (int kc = 0; kc < NK; kc++) {
        asm volatile("cp.async.wait_group 1;" ::: "memory");
        __syncthreads();
        const uint32_t bA  = sb + (uint32_t)((kc % NSTG) * STAGE_F);
        const uint32_t bAl = bA + TILE_B;
        const uint32_t bB  = bA + 2 * TILE_B;
#pragma unroll
        for (int kh = 0; kh < 2; kh++) {
            uint32_t fb[2][4];
#pragma unroll
            for (int nt2 = 0; nt2 < 2; nt2++) {
                const int rr = wn * 32 + nt2 * 16 + rb;
                const int cc = kh * 2 + cb;
                ldmx4(fb[nt2], bB + sw_off(rr, cc));
            }
#pragma unroll
            for (int mt = 0; mt < 4; mt++) {
                uint32_t fah[4], fal[4];
                const int rr = wm * 64 + mt * 16 + ra;
                const int cc = kh * 2 + ca;
                ldmx4(fah, bA  + sw_off(rr, cc));
                ldmx4(fal, bAl + sw_off(rr, cc));
#pragma unroll
                for (int nt = 0; nt < 4; nt++) {
                    const uint32_t b0 = fb[nt >> 1][(nt & 1) * 2];
                    const uint32_t b1 = fb[nt >> 1][(nt & 1) * 2 + 1];
                    mma_hf(acc[mt][nt], fah, b0, b1);
                    mma_hf(acc[mt][nt], fal, b0, b1);
                }
            }
        }
        if (kc + 2 < NK) LOAD_STAGE((kc + 2) % NSTG, (kc + 2) * 32);
        asm volatile("cp.async.commit_group;" ::: "memory");
    }
    __syncthreads();
#undef LOAD_STAGE

    const int group = lane >> 2, tid4 = lane & 3;
    if (flags & 4) {
        // cat epilogue: transpose through smem, write single fp16 with relu
        const int dIdx = zoff + (z >> 1);
        const int bpp = dIdx / 9, ap = dIdx % 9;
        __half* outT = t ? catr : catc;
        float* smf = (float*)smem;
#pragma unroll
        for (int mt = 0; mt < 4; mt++)
#pragma unroll
            for (int nt = 0; nt < 4; nt++) {
                const int ml = wm * 64 + mt * 16 + group;
                const int nl = wn * 32 + nt * 8 + tid4 * 2;
                smf[nl * 128 + ml]           = acc[mt][nt][0];
                smf[(nl + 1) * 128 + ml]     = acc[mt][nt][1];
                smf[nl * 128 + ml + 8]       = acc[mt][nt][2];
                smf[(nl + 1) * 128 + ml + 8] = acc[mt][nt][3];
            }
        __syncthreads();
        const int nl = tid >> 1, half = tid & 1;
        const float* row = smf + nl * 128 + half * 64;
        __half* oh = outT + (size_t)(bpp * NPAD + n0 + nl) * KTOT + ap * 256 + m0 + half * 64;
#pragma unroll
        for (int g = 0; g < 8; g++) {
            __half hs[8];
#pragma unroll
            for (int j = 0; j < 8; j++)
                hs[j] = __float2half_rn(fmaxf(row[g * 8 + j], 0.f));
            *(uint4*)(oh + g * 8) = make_uint4(hpack(hs[0],hs[1]), hpack(hs[2],hs[3]),
                                               hpack(hs[4],hs[5]), hpack(hs[6],hs[7]));
        }
    } else {
        float* oF = outF + (size_t)z * outStride;
#pragma unroll
        for (int mt = 0; mt < 4; mt++) {
            const int mA = m0 + wm * 64 + mt * 16 + group;
            const int mB = mA + 8;
            const float bvA = ((flags & 1) && mA < M) ? bias[mA] : 0.f;
            const float bvB = ((flags & 1) && mB < M) ? bias[mB] : 0.f;
#pragma unroll
            for (int nt = 0; nt < 4; nt++) {
                const int n = n0 + wn * 32 + nt * 8 + tid4 * 2;
#pragma unroll
                for (int e = 0; e < 2; e++) {
                    if (n + e < HW) {
                        if (mA < M) oF[(size_t)mA * HW + n + e] = acc[mt][nt][e] + bvA;
                        if (mB < M) oF[(size_t)mB * HW + n + e] = acc[mt][nt][2 + e] + bvB;
                    }
                }
            }
        }
    }
}

// ============ fp16 2-term implicit conv GEMM (towers + pred) ============
// flags: 1=bias 2=relu 8=z-parity 16=feat-out(fp16 x3 copies) 32=fp32-p-out 64=also f32 copy
__global__ __launch_bounds__(256, 2) void conv_f16(
    const __half* __restrict__ Wh, const __half* __restrict__ Wl, int arowE, int arowO,
    const __half* __restrict__ fIn, int cmul, int cadd, int cshift,
    const float* __restrict__ biasE, const float* __restrict__ biasO,
    float* __restrict__ outF, size_t outStride,
    __half* __restrict__ oFeat, float* __restrict__ oF32,
    int M, int flags)
{
    extern __shared__ char smem[];
    const uint32_t sb = smem_u32(smem);
    const int tid = threadIdx.x, lane = tid & 31, w = tid >> 5;
    const int wm = w >> 2, wn = w & 3;
    const int m0 = blockIdx.y * 128, n0 = blockIdx.x * 128;
    const int z = blockIdx.z;
    const int inChain = ((z * cmul) + cadd) >> cshift;

    const bool odd = (flags & 8) && (z & 1);
    const int arow = odd ? arowO : arowE;
    const float* bias = odd ? biasO : biasE;

    const __half* srcA[2] = {Wh + ((size_t)arow + m0) * KTOT, Wl + ((size_t)arow + m0) * KTOT};
    const __half* fbase = fIn + (size_t)inChain * 256 * CH112 + n0;

    float acc[4][4][4];
#pragma unroll
    for (int i = 0; i < 4; i++)
#pragma unroll
        for (int j = 0; j < 4; j++)
#pragma unroll
            for (int q = 0; q < 4; q++) acc[i][j][q] = 0.f;

    const int ra = (lane & 15);
    const int ca = lane >> 4;

#define LOAD_CSTAGE(s, kc) do { \
    const int _t = (kc) >> 3, _c0 = ((kc) & 7) << 5; \
    const long _toff = (long)c_dxsel[_t] * (long)FC4 + (long)c_dy9[_t] * 112; \
    _Pragma("unroll") \
    for (int t2 = 0; t2 < 2; t2++) { \
        const uint32_t baseA = sb + (uint32_t)((s) * STAGE_F + t2 * TILE_B); \
        _Pragma("unroll") \
        for (int h = 0; h < 2; h++) { \
            const int q = tid + h * 256; \
            const int r = q >> 2, c = q & 3; \
            cp16(baseA + sw_off(r, c), srcA[t2] + (size_t)r * KTOT + (kc) * 32 + c * 8); \
        } \
    } \
    { \
        const uint32_t baseB = sb + (uint32_t)((s) * STAGE_F + 2 * TILE_B); \
        _Pragma("unroll") \
        for (int h = 0; h < 2; h++) { \
            const int q = tid + h * 256; \
            const int r = q >> 4, c = q & 15; \
            cp16(baseB + swb_off(r, c), fbase + _toff + (size_t)(_c0 + r) * CH112 + c * 8); \
        } \
    } \
} while (0)

    LOAD_CSTAGE(0, 0);
    asm volatile("cp.async.commit_group;" ::: "memory");
    LOAD_CSTAGE(1, 1);
    asm volatile("cp.async.commit_group;" ::: "memory");

    for (int kc = 0; kc < NK; kc++) {
        asm volatile("cp.async.wait_group 1;" ::: "memory");
        __syncthreads();
        const uint32_t bA  = sb + (uint32_t)((kc % NSTG) * STAGE_F);
        const uint32_t bAl = bA + TILE_B;
        const uint32_t bB  = bA + 2 * TILE_B;
#pragma unroll
        for (int kh = 0; kh < 2; kh++) {
            const int rowl = kh * 16 + (lane & 15);
            uint32_t fb[2][4];
#pragma unroll
            for (int nt2 = 0; nt2 < 2; nt2++) {
                const int chunk = wn * 4 + nt2 * 2 + (lane >> 4);
                ldmx4t(fb[nt2], bB + swb_off(rowl, chunk));
            }
#pragma unroll
            for (int mt = 0; mt < 4; mt++) {
                uint32_t fah[4], fal[4];
                const int rr = wm * 64 + mt * 16 + ra;
                const int cc = kh * 2 + ca;
                ldmx4(fah, bA  + sw_off(rr, cc));
                ldmx4(fal, bAl + sw_off(rr, cc));
#pragma unroll
                for (int nt = 0; nt < 4; nt++) {
                    const uint32_t b0 = fb[nt >> 1][(nt & 1) * 2];
                    const uint32_t b1 = fb[nt >> 1][(nt & 1) * 2 + 1];
                    mma_hf(acc[mt][nt], fah, b0, b1);
                    mma_hf(acc[mt][nt], fal, b0, b1);
                }
            }
        }
        if (kc + 2 < NK) LOAD_CSTAGE((kc + 2) % NSTG, kc + 2);
        asm volatile("cp.async.commit_group;" ::: "memory");
    }
    __syncthreads();
#undef LOAD_CSTAGE

    const int group = lane >> 2, tid4 = lane & 3;
#pragma unroll
    for (int mt = 0; mt < 4; mt++) {
        const int mA = m0 + wm * 64 + mt * 16 + group;
        const int mB = mA + 8;
        const float bvA = ((flags & 1) && mA < M) ? bias[mA] : 0.f;
        const float bvB = ((flags & 1) && mB < M) ? bias[mB] : 0.f;
#pragma unroll
        for (int nt = 0; nt < 4; nt++) {
            const int n = n0 + wn * 32 + nt * 8 + tid4 * 2;
#pragma unroll
            for (int e = 0; e < 2; e++) {
                const int p2 = n + e;
                if (p2 >= NPIX) continue;
                const int xq = p2 % 112;
                if (xq >= 100) continue;
                if (flags & 16) {
#pragma unroll
                    for (int half = 0; half < 2; half++) {
                        const int m = half ? mB : mA;
                        float v = (half ? acc[mt][nt][2 + e] : acc[mt][nt][e]) + (half ? bvB : bvA);
                        v = fmaxf(v, 0.f);
                        const __half h = __float2half_rn(v);
                        const size_t cb = (size_t)(z * 256 + m) * CH112;
                        if (flags & 64) oF32[cb + p2] = v;
#pragma unroll
                        for (int j = 0; j < 3; j++) {
                            const int q = p2 - (j - 1);
                            if (q >= 0) oFeat[(size_t)j * FC4 + cb + q] = h;
                        }
                    }
                } else {
                    const int p = (p2 / 112) * 100 + xq;
                    float* oF = outF + (size_t)z * outStride;
                    if (mA < M) oF[(size_t)mA * HW + p] = acc[mt][nt][e] + bvA;
                    if (mB < M) oF[(size_t)mB * HW + p] = acc[mt][nt][2 + e] + bvB;
                }
            }
        }
    }
}

// ============ small kernels ============
// fp16 hi/lo weight split; tap=1 remaps k: dst tap*256+c <- src c*9+tap
__global__ void wsplit_f16(const float* __restrict__ src, __half* __restrict__ h,
                           __half* __restrict__ l, int M, int Mp, int tap)
{
    const int idx = blockIdx.x * blockDim.x + threadIdx.x;
    if (idx >= Mp * KTOT) return;
    const int m = idx / KTOT, kk = idx % KTOT;
    float v = 0.f;
    if (m < M) {
        const int ks = tap ? ((kk & 255) * 9 + (kk >> 8)) : kk;
        v = src[(size_t)m * KTOT + ks];
    }
    const __half hh = __float2half_rn(v);
    h[idx] = hh;
    l[idx] = __float2half_rn(v - __half2float(hh));
}

// x -> fp16, 112-padded rows, 3 shifted copies, chains 0,1
__global__ void xsplit3_f16(const float* __restrict__ x, __half* __restrict__ o)
{
    const int idx = blockIdx.x * blockDim.x + threadIdx.x;
    if (idx >= 2 * 256 * NPIX) return;
    const int p2 = idx % NPIX;
    const int ch = idx / NPIX;
    const int xq = p2 % 112;
    if (xq >= 100) return;
    const float v = x[(size_t)ch * HW + (p2 / 112) * 100 + xq];
    const __half h = __float2half_rn(v);
    const size_t cb = (size_t)ch * CH112;
#pragma unroll
    for (int j = 0; j < 3; j++) {
        const int q = p2 - (j - 1);
        if (q >= 0) o[(size_t)j * FC4 + cb + q] = h;
    }
}

// fused deform gather (cls + reg): fp32 source, fp16 col out, 6 slots per phase
__global__ __launch_bounds__(256) void im2col_def_f16(
    const float* __restrict__ f32, const float* __restrict__ boxreg,
    __half* __restrict__ colBase, int base3)
{
    const int zl = blockIdx.y;
    const int dIdx = base3 + zl;
    const int bpp = dIdx / 9, ap = dIdx % 9;
    const int nn = ap * 2 + bpp, bb = nn / 9, aa = nn % 9;
    const float aw = c_AW[aa], ah_ = c_AH[aa];
    const int idx = blockIdx.x * 256 + threadIdx.x;
    if (idx >= NPAD * 32) return;
    const int p = idx % NPAD, cblk = idx / NPAD;
    __half* o0 = colBase + (size_t)(zl * 2)     * CSTR + (size_t)p * KTOT + cblk * 72;
    __half* o1 = colBase + (size_t)(zl * 2 + 1) * CSTR + (size_t)p * KTOT + cblk * 72;
    if (p >= HW) {
        const uint4 zz = make_uint4(0, 0, 0, 0);
#pragma unroll
        for (int g = 0; g < 9; g++) { *(uint4*)(o0 + g * 8) = zz; *(uint4*)(o1 + g * 8) = zz; }
        return;
    }
    const float* br = boxreg + (size_t)bb * 36 * HW + (size_t)aa * 4 * HW + p;
    const int y = p / WID, x = p % WID;
    const float r0 = br[0], r1 = br[HW], r2 = br[2 * HW], r3 = br[3 * HW];
    const float whx = aw * expf(r2), why = ah_ * expf(r3);
    const float tlx = aw * r0 - 0.5f * whx, tly = ah_ * r1 - 0.5f * why;
    const float gxv[3] = {tlx, tlx + 0.5f * whx, tlx + whx};
    const float gyv[3] = {tly, tly + 0.5f * why, tly + why};
    int O00[9], O01[9], O10[9], O11[9];
    float W00[9], W01[9], W10[9], W11[9];
#pragma unroll
    for (int i = 0; i < 3; i++) {
        const float pxf = (float)x + gyv[i];
        const float x0f = floorf(pxf);
        const float lx = pxf - x0f;
        const int ix0 = (int)x0f;
        const bool vx0 = (ix0 >= 0) && (ix0 < WID), vx1 = (ix0 + 1 >= 0) && (ix0 + 1 < WID);
        const int xc0 = min(max(ix0, 0), WID - 1), xc1 = min(max(ix0 + 1, 0), WID - 1);
#pragma unroll
        for (int j = 0; j < 3; j++) {
            const int k = i * 3 + j;
            const float pyf = (float)y + gxv[j];
            const float y0f = floorf(pyf);
            const float ly = pyf - y0f;
            const int iy0 = (int)y0f;
            const bool vy0 = (iy0 >= 0) && (iy0 < WID), vy1 = (iy0 + 1 >= 0) && (iy0 + 1 < WID);
            const int yc0 = min(max(iy0, 0), WID - 1), yc1 = min(max(iy0 + 1, 0), WID - 1);
            O00[k] = yc0 * 112 + xc0; O01[k] = yc0 * 112 + xc1;
            O10[k] = yc1 * 112 + xc0; O11[k] = yc1 * 112 + xc1;
            W00[k] = (vy0 && vx0) ? (1.f - ly) * (1.f - lx) : 0.f;
            W01[k] = (vy0 && vx1) ? (1.f - ly) * lx : 0.f;
            W10[k] = (vy1 && vx0) ? ly * (1.f - lx) : 0.f;
            W11[k] = (vy1 && vx1) ? ly * lx : 0.f;
        }
    }
#pragma unroll
    for (int t = 0; t < 2; t++) {
        const float* f0 = f32 + (size_t)((bpp * 2 + t) * 256) * CH112;
        __half* out = t ? o1 : o0;
#pragma unroll 1
        for (int g = 0; g < 9; g++) {
            __half hs[8];
#pragma unroll
            for (int j = 0; j < 8; j++) {
                const int e = g * 8 + j, cc = e / 9, k = e - cc * 9;
                const float* f = f0 + (size_t)(cblk * 8 + cc) * CH112;
                hs[j] = __float2half_rn(W00[k]*f[O00[k]] + W01[k]*f[O01[k]]
                                      + W10[k]*f[O10[k]] + W11[k]*f[O11[k]]);
            }
            *(uint4*)(out + g * 8) = make_uint4(hpack(hs[0],hs[1]), hpack(hs[2],hs[3]),
                                                hpack(hs[4],hs[5]), hpack(hs[6],hs[7]));
        }
    }
}

__global__ void delta_kernel(const float* __restrict__ boxreg, const float* __restrict__ refine,
                             float* __restrict__ out)
{
    const int idx = blockIdx.x * blockDim.x + threadIdx.x;
    if (idx >= 2 * 36 * HW) return;
    const int p = idx % HW, ch = (idx / HW) % 36, b = idx / (36 * HW), c = ch & 3;
    const float o1 = boxreg[((size_t)b * 36 + ch) * HW + p];
    const float o2 = refine[((size_t)b * 36 + ch) * HW + p];
    float v;
    if (c < 2) v = o1 + expf(boxreg[((size_t)b * 36 + ch + 2) * HW + p]) * o2;
    else       v = o1 + o2;
    out[idx] = v;
}

#define W_CLS   0
#define W_REG   1024
#define W_PRED  2048
#define W_DCLS  2176
#define W_DREG  2432
#define W_LOGIT 2688
#define W_REFIN 3456

static cudaStream_t s_gather = nullptr;
static cudaEvent_t s_evG[6], s_evM[6], s_evFork, s_evJoin;
static void ensure_streams() {
    if (!s_gather) {
        cudaStreamCreateWithFlags(&s_gather, cudaStreamNonBlocking);
        for (int i = 0; i < 6; i++) {
            cudaEventCreateWithFlags(&s_evG[i], cudaEventDisableTiming);
            cudaEventCreateWithFlags(&s_evM[i], cudaEventDisableTiming);
        }
        cudaEventCreateWithFlags(&s_evFork, cudaEventDisableTiming);
        cudaEventCreateWithFlags(&s_evJoin, cudaEventDisableTiming);
    }
}

#define NT_CONV 88

extern "C" void kernel_launch(void* const* d_in, const int* in_sizes, int n_in,
                              void* d_out, int out_size)
{
    const float* x        = (const float*)d_in[0];
    const float* cls_w    = (const float*)d_in[1];
    const float* cls_b    = (const float*)d_in[2];
    const float* reg_w    = (const float*)d_in[3];
    const float* reg_b    = (const float*)d_in[4];
    const float* pred_w   = (const float*)d_in[5];
    const float* pred_b   = (const float*)d_in[6];
    const float* dcls_w   = (const float*)d_in[7];
    const float* dreg_w   = (const float*)d_in[8];
    const float* logit_w  = (const float*)d_in[9];
    const float* logit_b  = (const float*)d_in[10];
    const float* refine_w = (const float*)d_in[11];
    const float* refine_b = (const float*)d_in[12];

    __half *wfh, *wfl, *colf, *catc, *catr, *fA, *fB;
    float *f32, *boxreg, *refine;
    cudaGetSymbolAddress((void**)&wfh, g_wfh);
    cudaGetSymbolAddress((void**)&wfl, g_wfl);
    cudaGetSymbolAddress((void**)&colf, g_colf);
    cudaGetSymbolAddress((void**)&catc, g_catc);
    cudaGetSymbolAddress((void**)&catr, g_catr);
    cudaGetSymbolAddress((void**)&fA, g_fA);
    cudaGetSymbolAddress((void**)&fB, g_fB);
    cudaGetSymbolAddress((void**)&f32, g_f32);
    cudaGetSymbolAddress((void**)&boxreg, g_boxreg);
    cudaGetSymbolAddress((void**)&refine, g_refine);
    fA += FGUARD; fB += FGUARD;

    cudaFuncSetAttribute(gemm_f16, cudaFuncAttributeMaxDynamicSharedMemorySize, SMEM_F);
    cudaFuncSetAttribute(conv_f16, cudaFuncAttributeMaxDynamicSharedMemorySize, SMEM_F);
    ensure_streams();

    auto wsp = [&](const float* src, int rowoff, int M, int Mp, int tap) {
        wsplit_f16<<<(Mp * KTOT + 255) / 256, 256>>>(
            src, wfh + (size_t)rowoff * KTOT, wfl + (size_t)rowoff * KTOT, M, Mp, tap);
    };
    wsp(cls_w, W_CLS, 1024, 1024, 1);
    wsp(reg_w, W_REG, 1024, 1024, 1);
    xsplit3_f16<<<(2 * 256 * NPIX + 255) / 256, 256>>>(x, fB);   // x in fB chains 0,1

    // ---- towers: L0 x(fB, cshift=1)->fA; L1 fA->fB; L2 fB->fA; L3 fA->fB (+f32) ----
    struct { const __half* in; int cshift; __half* out; int xf; } L[4] = {
        {fB, 1, fA, 0}, {fA, 0, fB, 0}, {fB, 0, fA, 0}, {fA, 0, fB, 64}};
    for (int layer = 0; layer < 4; layer++) {
        dim3 grid(NT_CONV, 2, 4);
        conv_f16<<<grid, 256, SMEM_F>>>(
            wfh, wfl, W_CLS + layer * 256, W_REG + layer * 256,
            L[layer].in, 1, 0, L[layer].cshift,
            cls_b + layer * 256, reg_b + layer * 256,
            nullptr, 0, L[layer].out, f32,
            256, 1 | 2 | 8 | 16 | L[layer].xf);
    }

    wsp(pred_w, W_PRED, 36, 128, 1);
    wsp(dcls_w, W_DCLS, 256, 256, 0);
    wsp(dreg_w, W_DREG, 256, 256, 0);
    wsp(logit_w, W_LOGIT, 720, 768, 0);
    wsp(refine_w, W_REFIN, 36, 128, 0);

    // ---- pred conv (rf chains = fB chains 1,3) ----
    {
        dim3 grid(NT_CONV, 1, 2);
        conv_f16<<<grid, 256, SMEM_F>>>(
            wfh, wfl, W_PRED, W_PRED,
            fB, 2, 1, 0,
            pred_b, pred_b,
            boxreg, (size_t)36 * HW, nullptr, nullptr, 36, 1 | 32);
    }

    // ---- deform: 6 fused phases (gather cls+reg on side stream; 6-z fp16 GEMM) ----
    {
        cudaEventRecord(s_evFork, 0);
        cudaStreamWaitEvent(s_gather, s_evFork, 0);
        const dim3 icg3(NPAD * 32 / 256, 3);
        const dim3 grid(NPAD / 128, 2, 6);
        for (int ph = 0; ph < 6; ph++) {
            const int base3 = ph * 3;
            __half* cb = colf + (size_t)(ph & 1) * 6 * CSTR;
            if (ph >= 2) cudaStreamWaitEvent(s_gather, s_evM[ph - 2], 0);
            im2col_def_f16<<<icg3, 256, 0, s_gather>>>(f32, boxreg, cb, base3);
            cudaEventRecord(s_evG[ph], s_gather);
            cudaStreamWaitEvent(0, s_evG[ph], 0);
            gemm_f16<<<grid, 256, SMEM_F>>>(
                wfh, wfl, W_DCLS, W_DREG, cb, nullptr, nullptr, 0,
                catc, catr, 256, 4 | 8, base3);
            cudaEventRecord(s_evM[ph], 0);
        }
        cudaEventRecord(s_evJoin, s_gather);
        cudaStreamWaitEvent(0, s_evJoin, 0);
    }

    // ---- 1x1 heads ----
    float* logits_out = (float*)d_out;
    float* delta_out = logits_out + (size_t)2 * 720 * HW;
    {
        dim3 gl(NPAD / 128, 6, 2);
        gemm_f16<<<gl, 256, SMEM_F>>>(
            wfh, wfl, W_LOGIT, W_LOGIT, catc, logit_b,
            logits_out, (size_t)720 * HW, nullptr, nullptr, 720, 1, 0);
        dim3 gr(NPAD / 128, 1, 2);
        gemm_f16<<<gr, 256, SMEM_F>>>(
            wfh, wfl, W_REFIN, W_REFIN, catr, refine_b,
            refine, (size_t)36 * HW, nullptr, nullptr, 36, 1, 0);
    }

    delta_kernel<<<(2 * 36 * HW + 255) / 256, 256>>>(boxreg, refine, delta_out);
}